// round 11
// baseline (speedup 1.0000x reference)
#include <cuda_runtime.h>
#include <math.h>
#include <cstdint>

#define Bn 4
#define Cc 256
#define Onc 256
#define Hh 64
#define Ww 64
#define Kk 9
#define HW 4096
#define NTHREADS 320

typedef unsigned long long u64;
typedef uint32_t u32;

// Scratch (static device arrays — no allocation)
__device__ float g_buf1[Bn * Cc * HW];
__device__ float g_buf2[Bn * Cc * HW];
__device__ float g_wT[3 * Cc * Kk * Onc];       // main weights [l][c][k][o]
__device__ float g_woT[3 * Cc * Kk * 28];       // offset weights [l][c][tap][28]

// ---- packed f32x2 helpers -------------------------------------------------
#define FMA2(d, a, b)  asm("fma.rn.f32x2 %0, %1, %2, %0;" : "+l"(d) : "l"(a), "l"(b))
#define ADDP2(d, a)    asm("add.rn.f32x2 %0, %1, %0;" : "+l"(d) : "l"(a))

__device__ __forceinline__ u64 pack2(float lo, float hi) {
    u64 r; asm("mov.b64 %0, {%1,%2};" : "=l"(r) : "f"(lo), "f"(hi)); return r;
}
__device__ __forceinline__ float2 unpack2(u64 v) {
    float2 f; asm("mov.b64 {%0,%1}, %2;" : "=f"(f.x), "=f"(f.y) : "l"(v)); return f;
}

// ---- cp.async helpers -----------------------------------------------------
__device__ __forceinline__ u32 smem_u32(const void* p) {
    u32 a;
    asm("{ .reg .u64 t; cvta.to.shared.u64 t, %1; cvt.u32.u64 %0, t; }" : "=r"(a) : "l"(p));
    return a;
}
#define CP_ASYNC16(dst, src) \
    asm volatile("cp.async.cg.shared.global [%0], [%1], 16;" :: "r"(dst), "l"(src))
#define CP_COMMIT() asm volatile("cp.async.commit_group;" ::: "memory")
#define CP_WAIT0()  asm volatile("cp.async.wait_group 0;" ::: "memory")

// ---------------------------------------------------------------------------
// Prep (merged over 3 layers)
// ---------------------------------------------------------------------------
__global__ void transpose_w_all(const float* __restrict__ w0, const float* __restrict__ w1,
                                const float* __restrict__ w2, float* __restrict__ wT)
{
    int idx = blockIdx.x * blockDim.x + threadIdx.x;
    if (idx >= 3 * Cc * Kk * Onc) return;
    int l   = idx / (Cc * Kk * Onc);
    int rem = idx - l * (Cc * Kk * Onc);
    int o = rem & (Onc - 1);
    int k = (rem >> 8) % Kk;
    int c = rem / (Kk * Onc);
    const float* w = (l == 0) ? w0 : (l == 1) ? w1 : w2;
    wT[idx] = w[((size_t)o * Cc + c) * Kk + k];
}

__global__ void transpose_woff_all(const float* __restrict__ w0, const float* __restrict__ w1,
                                   const float* __restrict__ w2, float* __restrict__ wT)
{
    int idx = blockIdx.x * blockDim.x + threadIdx.x;
    if (idx >= 3 * Cc * Kk * 28) return;
    int l   = idx / (Cc * Kk * 28);
    int rem = idx - l * (Cc * Kk * 28);
    int oc  = rem % 28;
    int tap = (rem / 28) % Kk;
    int c   = rem / (Kk * 28);
    const float* w = (l == 0) ? w0 : (l == 1) ? w1 : w2;
    wT[idx] = (oc < 27) ? w[((size_t)oc * Cc + c) * Kk + tap] : 0.f;
}

// ---------------------------------------------------------------------------
// Dynamic smem layout (bytes), total 64512, 2 CTAs/SM:
//   [0,     9216)   swgt float4[576]
//   [9216,  18432)  sidx int4[576]
//   [18432, 27648)  ssm[2][1152]   (double-buffered samples)
//   [27648, 64512)  wsm[2][4608]   (double-buffered weights)
// Phase-1 overlays: xs[16][120] at 0 (7680) + wo[16*252] at 7680 (16128);
//                   om[2][64][28] at 27648 (14336).
// ---------------------------------------------------------------------------
#define SWGT_O  0
#define SIDX_O  9216
#define SSM_O   18432
#define WSM_O   27648
#define XS_O    0
#define WO_O    7680
#define OM_O    27648
#define SMEMSZ  64512

__global__ __launch_bounds__(NTHREADS, 2) void dcn_fused_kernel(
    const float* __restrict__ x,
    const float* __restrict__ w_offT,  // [C][9][28]
    const float* __restrict__ b_off,   // [27]
    const float* __restrict__ wT,      // [C][9][O]
    const float* __restrict__ bias,    // [O]
    float* __restrict__ out)
{
    extern __shared__ __align__(16) char smem[];
    float4* swgt = (float4*)(smem + SWGT_O);
    int4*   sidx = (int4*)(smem + SIDX_O);

    int b   = blockIdx.y;
    int t   = blockIdx.x;             // 0..63
    int py0 = (t >> 3) * 8;
    int px0 = (t & 7) * 8;
    int tid = threadIdx.x;
    bool worker = (tid < 256);        // phase-1 compute + phase-2 GEMM role

    // ======================== Phase 1: offset conv ========================
    {
        float* xs_s = (float*)(smem + XS_O);           // [16][120]
        float* wo_s = (float*)(smem + WO_O);           // [16*252]
        float (*om_s)[64][28] = (float (*)[64][28])(smem + OM_O);

        int p   = tid & 63;
        int g   = (tid >> 6) & 3;
        int ppy = p >> 3;
        int ppx = p & 7;

        u64 aoff2[14];
#pragma unroll
        for (int j = 0; j < 14; j++) aoff2[j] = 0ull;

        float  hpf[8];
        float4 wpf[4];

        // prefetch round 0 (workers only)
        if (worker) {
            const float4* wp4 = (const float4*)w_offT;
#pragma unroll
            for (int i8 = 0; i8 < 8; i8++) {
                int i = tid + 256 * i8;
                float v = 0.f;
                if (i < 1920) {
                    int ch  = i / 120;
                    int rem = i - ch * 120;
                    int rr  = rem / 12;
                    int cc2 = rem - rr * 12;
                    int gy  = py0 - 1 + rr;
                    int gx  = px0 - 1 + cc2;
                    if (cc2 < 10 && (unsigned)gy < (unsigned)Hh && (unsigned)gx < (unsigned)Ww)
                        v = __ldg(x + ((size_t)(b * Cc + ch)) * HW + gy * Ww + gx);
                }
                hpf[i8] = v;
            }
#pragma unroll
            for (int i4 = 0; i4 < 4; i4++) {
                int i = tid + 256 * i4;
                if (i < 1008) wpf[i4] = __ldg(wp4 + i);
            }
        }

        for (int r = 0; r < 16; r++) {
            __syncthreads();
            if (worker) {
#pragma unroll
                for (int i8 = 0; i8 < 8; i8++) {
                    int i = tid + 256 * i8;
                    if (i < 1920) {
                        int ch  = i / 120;
                        int rem = i - ch * 120;
                        xs_s[ch * 120 + rem] = hpf[i8];
                    }
                }
                float4* wo4 = (float4*)wo_s;
#pragma unroll
                for (int i4 = 0; i4 < 4; i4++) {
                    int i = tid + 256 * i4;
                    if (i < 1008) wo4[i] = wpf[i4];
                }
            }
            __syncthreads();

            if (worker) {
                if (r < 15) {
                    int rn = r + 1;
                    const float4* wp4 = (const float4*)(w_offT + (size_t)(rn << 4) * 252);
#pragma unroll
                    for (int i8 = 0; i8 < 8; i8++) {
                        int i = tid + 256 * i8;
                        float v = 0.f;
                        if (i < 1920) {
                            int ch  = i / 120;
                            int rem = i - ch * 120;
                            int rr  = rem / 12;
                            int cc2 = rem - rr * 12;
                            int c   = (rn << 4) + ch;
                            int gy  = py0 - 1 + rr;
                            int gx  = px0 - 1 + cc2;
                            if (cc2 < 10 && (unsigned)gy < (unsigned)Hh && (unsigned)gx < (unsigned)Ww)
                                v = __ldg(x + ((size_t)(b * Cc + c)) * HW + gy * Ww + gx);
                        }
                        hpf[i8] = v;
                    }
#pragma unroll
                    for (int i4 = 0; i4 < 4; i4++) {
                        int i = tid + 256 * i4;
                        if (i < 1008) wpf[i4] = __ldg(wp4 + i);
                    }
                }

#pragma unroll
                for (int ci = 0; ci < 4; ci++) {
                    int ch = (g << 2) + ci;
                    const float* xrow = xs_s + ch * 120;
                    float xv[9];
#pragma unroll
                    for (int rr = 0; rr < 3; rr++)
#pragma unroll
                        for (int cc = 0; cc < 3; cc++)
                            xv[rr * 3 + cc] = xrow[(ppy + rr) * 12 + ppx + cc];

#pragma unroll
                    for (int tap = 0; tap < 9; tap++) {
                        u64 xt2 = pack2(xv[tap], xv[tap]);
                        const ulonglong2* wr = (const ulonglong2*)(wo_s + ch * 252 + tap * 28);
#pragma unroll
                        for (int j = 0; j < 7; j++) {
                            ulonglong2 wv2 = wr[j];
                            FMA2(aoff2[2 * j],     xt2, wv2.x);
                            FMA2(aoff2[2 * j + 1], xt2, wv2.y);
                        }
                    }
                }
            }
        }
        __syncthreads();
        if (worker && (tid >> 6) >= 2) {
#pragma unroll
            for (int j = 0; j < 14; j++)
                *(u64*)&om_s[(tid >> 6) - 2][p][2 * j] = aoff2[j];
        }
        __syncthreads();
        if (worker && (tid >> 6) < 2) {
#pragma unroll
            for (int j = 0; j < 14; j++) {
                u64 tacc = *(u64*)&om_s[g][p][2 * j];
                ADDP2(tacc, aoff2[j]);
                *(u64*)&om_s[g][p][2 * j] = tacc;
            }
        }
        __syncthreads();

        // ---- Coordinate / gather-weight precompute (direct write) ----
        for (int i = tid; i < 576; i += NTHREADS) {
            int pp = i & 63;
            int k  = i >> 6;
            int gy = py0 + (pp >> 3);
            int gx = px0 + (pp & 7);
            float dy = __ldg(b_off + 2 * k)     + om_s[0][pp][2 * k]     + om_s[1][pp][2 * k];
            float dx = __ldg(b_off + 2 * k + 1) + om_s[0][pp][2 * k + 1] + om_s[1][pp][2 * k + 1];
            float mr = __ldg(b_off + 18 + k)    + om_s[0][pp][18 + k]    + om_s[1][pp][18 + k];
            float mv = 1.f / (1.f + expf(-mr));
            float ysv = (float)gy + (float)(k / 3 - 1) + dy;
            float xsv = (float)gx + (float)(k % 3 - 1) + dx;
            float y0f = floorf(ysv), x0f = floorf(xsv);
            float wy = ysv - y0f, wx = xsv - x0f;
            int y0 = (int)y0f, x0 = (int)x0f;
            int y1 = y0 + 1, x1 = x0 + 1;
            bool vy0 = (y0 >= 0) && (y0 < Hh);
            bool vy1 = (y1 >= 0) && (y1 < Hh);
            bool vx0 = (x0 >= 0) && (x0 < Ww);
            bool vx1 = (x1 >= 0) && (x1 < Ww);
            int y0c = min(max(y0, 0), Hh - 1), y1c = min(max(y1, 0), Hh - 1);
            int x0c = min(max(x0, 0), Ww - 1), x1c = min(max(x1, 0), Ww - 1);
            float4 wv;
            wv.x = (vy0 && vx0) ? mv * (1.f - wy) * (1.f - wx) : 0.f;
            wv.y = (vy0 && vx1) ? mv * (1.f - wy) * wx         : 0.f;
            wv.z = (vy1 && vx0) ? mv * wy * (1.f - wx)         : 0.f;
            wv.w = (vy1 && vx1) ? mv * wy * wx                 : 0.f;
            int4 iv;
            iv.x = y0c * Ww + x0c;
            iv.y = y0c * Ww + x1c;
            iv.z = y1c * Ww + x0c;
            iv.w = y1c * Ww + x1c;
            swgt[i] = wv;
            sidx[i] = iv;
        }
        __syncthreads();
    }

    // ====== Phase 2: producer/consumer warp-specialized sampled GEMM ======
    const float* xb = x + (size_t)b * Cc * HW;
    float* ssmb = (float*)(smem + SSM_O);
    u32 wsm_base = smem_u32(smem + WSM_O);

    if (worker) {
        // ---------------- consumer: pure GEMM ----------------
        int to = tid >> 4;   // 0..15 -> o-base = to*16
        int tp = tid & 15;   // 0..15 -> p-base = tp*4

        u64 acc2[8][4];
#pragma unroll
        for (int i = 0; i < 8; i++)
#pragma unroll
            for (int j = 0; j < 4; j++) acc2[i][j] = 0ull;

        __syncthreads();     // prologue: chunk-0 buffers ready

        for (int j = 0; j < 128; j++) {
            int s = j & 1;
            const float* wsm = (const float*)(smem + WSM_O + s * 18432);
            const float* ssm = ssmb + s * 1152;
#pragma unroll
            for (int cc = 0; cc < 2; cc++) {
#pragma unroll
                for (int k = 0; k < 9; k++) {
                    const float* wr = wsm + cc * 2304 + k * 256 + (to << 4);
                    ulonglong2 w01 = *(const ulonglong2*)(wr);
                    ulonglong2 w23 = *(const ulonglong2*)(wr + 4);
                    ulonglong2 w45 = *(const ulonglong2*)(wr + 8);
                    ulonglong2 w67 = *(const ulonglong2*)(wr + 12);
                    float4 sv = *(const float4*)(ssm + cc * 576 + k * 64 + (tp << 2));
                    u64 sp[4];
                    sp[0] = pack2(sv.x, sv.x);
                    sp[1] = pack2(sv.y, sv.y);
                    sp[2] = pack2(sv.z, sv.z);
                    sp[3] = pack2(sv.w, sv.w);
                    u64 wp[8] = {w01.x, w01.y, w23.x, w23.y, w45.x, w45.y, w67.x, w67.y};
#pragma unroll
                    for (int op = 0; op < 8; op++)
#pragma unroll
                        for (int jj = 0; jj < 4; jj++)
                            FMA2(acc2[op][jj], wp[op], sp[jj]);
                }
            }
            __syncthreads();
        }

        // epilogue: bias + ReLU, vectorized stores
        int row = tp >> 1;
        int cb  = (tp & 1) << 2;
#pragma unroll
        for (int op = 0; op < 8; op++) {
            int o0 = (to << 4) + (op << 1);
            float bv0 = __ldg(bias + o0);
            float bv1 = __ldg(bias + o0 + 1);
            float2 v0 = unpack2(acc2[op][0]);
            float2 v1 = unpack2(acc2[op][1]);
            float2 v2 = unpack2(acc2[op][2]);
            float2 v3 = unpack2(acc2[op][3]);
            float4 lo, hi;
            lo.x = fmaxf(v0.x + bv0, 0.f); lo.y = fmaxf(v1.x + bv0, 0.f);
            lo.z = fmaxf(v2.x + bv0, 0.f); lo.w = fmaxf(v3.x + bv0, 0.f);
            hi.x = fmaxf(v0.y + bv1, 0.f); hi.y = fmaxf(v1.y + bv1, 0.f);
            hi.z = fmaxf(v2.y + bv1, 0.f); hi.w = fmaxf(v3.y + bv1, 0.f);
            size_t base0 = ((size_t)(b * Onc + o0) * Hh + py0 + row) * Ww + px0 + cb;
            size_t base1 = base0 + (size_t)Hh * Ww;
            *(float4*)(out + base0) = lo;
            *(float4*)(out + base1) = hi;
        }
    } else {
        // ---------------- producer: sampling + weight cp.async ----------------
        int ptid = tid - 256;   // 0..63

        // prologue: fill chunk-0 buffers (buffer 0)
        {
            const float4* wp4 = (const float4*)wT;
            u32 wdst = wsm_base + ptid * 16;
#pragma unroll
            for (int q = 0; q < 18; q++)
                CP_ASYNC16(wdst + q * 1024, wp4 + ptid + 64 * q);
            CP_COMMIT();
#pragma unroll
            for (int q = 0; q < 18; q++) {
                int i  = ptid + 64 * q;
                int cc = (i >= 576);
                int r  = i - (cc ? 576 : 0);
                float4 wv = swgt[r];
                int4   iv = sidx[r];
                const float* xp = xb + (size_t)cc * HW;
                ssmb[i] = wv.x * __ldg(xp + iv.x) + wv.y * __ldg(xp + iv.y)
                        + wv.z * __ldg(xp + iv.z) + wv.w * __ldg(xp + iv.w);
            }
            CP_WAIT0();
        }
        __syncthreads();

        for (int j = 0; j < 128; j++) {
            if (j < 127) {
                int sn = (j + 1) & 1;
                int c0 = (j + 1) * 2;
                const float4* wp4 = (const float4*)(wT + (size_t)c0 * 2304);
                u32 wdst = wsm_base + sn * 18432 + ptid * 16;
#pragma unroll
                for (int q = 0; q < 18; q++)
                    CP_ASYNC16(wdst + q * 1024, wp4 + ptid + 64 * q);
                CP_COMMIT();
                float* ssm = ssmb + sn * 1152;
                const float* xp0 = xb + (size_t)c0 * HW;
#pragma unroll
                for (int q = 0; q < 18; q++) {
                    int i  = ptid + 64 * q;
                    int cc = (i >= 576);
                    int r  = i - (cc ? 576 : 0);
                    float4 wv = swgt[r];
                    int4   iv = sidx[r];
                    const float* xp = xp0 + cc * HW;
                    ssm[i] = wv.x * __ldg(xp + iv.x) + wv.y * __ldg(xp + iv.y)
                           + wv.z * __ldg(xp + iv.z) + wv.w * __ldg(xp + iv.w);
                }
                CP_WAIT0();
            }
            __syncthreads();
        }
    }
}

// ---------------------------------------------------------------------------
// Launch
// ---------------------------------------------------------------------------
extern "C" void kernel_launch(void* const* d_in, const int* in_sizes, int n_in,
                              void* d_out, int out_size)
{
    const float* x = (const float*)d_in[0];
    const float* w_off[3] = {(const float*)d_in[1], (const float*)d_in[5], (const float*)d_in[9]};
    const float* b_off[3] = {(const float*)d_in[2], (const float*)d_in[6], (const float*)d_in[10]};
    const float* wq[3]    = {(const float*)d_in[3], (const float*)d_in[7], (const float*)d_in[11]};
    const float* bias[3]  = {(const float*)d_in[4], (const float*)d_in[8], (const float*)d_in[12]};

    float *buf1, *buf2, *wT, *woT;
    cudaGetSymbolAddress((void**)&buf1, g_buf1);
    cudaGetSymbolAddress((void**)&buf2, g_buf2);
    cudaGetSymbolAddress((void**)&wT, g_wT);
    cudaGetSymbolAddress((void**)&woT, g_woT);

    cudaFuncSetAttribute(dcn_fused_kernel, cudaFuncAttributeMaxDynamicSharedMemorySize, SMEMSZ);

    transpose_w_all<<<(3 * Cc * Kk * Onc + 255) / 256, 256>>>(wq[0], wq[1], wq[2], wT);
    transpose_woff_all<<<(3 * Cc * Kk * 28 + 255) / 256, 256>>>(w_off[0], w_off[1], w_off[2], woT);

    const float* src[3] = {x, buf1, buf2};
    float*       dst[3] = {buf1, buf2, (float*)d_out};

    for (int l = 0; l < 3; l++) {
        dcn_fused_kernel<<<dim3(64, Bn), NTHREADS, SMEMSZ>>>(src[l],
                                                             woT + (size_t)l * Cc * Kk * 28,
                                                             b_off[l],
                                                             wT + (size_t)l * Cc * Kk * Onc,
                                                             bias[l], dst[l]);
    }
}

// round 12
// speedup vs baseline: 1.2341x; 1.2341x over previous
#include <cuda_runtime.h>
#include <math.h>
#include <cstdint>

#define Bn 4
#define Cc 256
#define Onc 256
#define Hh 64
#define Ww 64
#define Kk 9
#define HW 4096

typedef unsigned long long u64;
typedef uint32_t u32;

// Scratch (static device arrays — no allocation)
__device__ float g_buf1[Bn * Cc * HW];
__device__ float g_buf2[Bn * Cc * HW];
__device__ float g_wT[3 * Cc * Kk * Onc];       // main weights [l][c][k][o]
__device__ float g_woT[3 * Cc * Kk * 28];       // offset weights [l][c][tap][28]

// ---- packed f32x2 helpers -------------------------------------------------
#define FMA2(d, a, b)  asm("fma.rn.f32x2 %0, %1, %2, %0;" : "+l"(d) : "l"(a), "l"(b))
#define ADDP2(d, a)    asm("add.rn.f32x2 %0, %1, %0;" : "+l"(d) : "l"(a))

__device__ __forceinline__ u64 pack2(float lo, float hi) {
    u64 r; asm("mov.b64 %0, {%1,%2};" : "=l"(r) : "f"(lo), "f"(hi)); return r;
}
__device__ __forceinline__ float2 unpack2(u64 v) {
    float2 f; asm("mov.b64 {%0,%1}, %2;" : "=f"(f.x), "=f"(f.y) : "l"(v)); return f;
}

// ---- cp.async helpers -----------------------------------------------------
__device__ __forceinline__ u32 smem_u32(const void* p) {
    u32 a;
    asm("{ .reg .u64 t; cvta.to.shared.u64 t, %1; cvt.u32.u64 %0, t; }" : "=r"(a) : "l"(p));
    return a;
}
#define CP_ASYNC16(dst, src) \
    asm volatile("cp.async.cg.shared.global [%0], [%1], 16;" :: "r"(dst), "l"(src))
#define CP_COMMIT() asm volatile("cp.async.commit_group;" ::: "memory")
#define CP_WAIT0()  asm volatile("cp.async.wait_group 0;" ::: "memory")

// ---------------------------------------------------------------------------
// Prep (merged over 3 layers)
// ---------------------------------------------------------------------------
__global__ void transpose_w_all(const float* __restrict__ w0, const float* __restrict__ w1,
                                const float* __restrict__ w2, float* __restrict__ wT)
{
    int idx = blockIdx.x * blockDim.x + threadIdx.x;
    if (idx >= 3 * Cc * Kk * Onc) return;
    int l   = idx / (Cc * Kk * Onc);
    int rem = idx - l * (Cc * Kk * Onc);
    int o = rem & (Onc - 1);
    int k = (rem >> 8) % Kk;
    int c = rem / (Kk * Onc);
    const float* w = (l == 0) ? w0 : (l == 1) ? w1 : w2;
    wT[idx] = w[((size_t)o * Cc + c) * Kk + k];
}

__global__ void transpose_woff_all(const float* __restrict__ w0, const float* __restrict__ w1,
                                   const float* __restrict__ w2, float* __restrict__ wT)
{
    int idx = blockIdx.x * blockDim.x + threadIdx.x;
    if (idx >= 3 * Cc * Kk * 28) return;
    int l   = idx / (Cc * Kk * 28);
    int rem = idx - l * (Cc * Kk * 28);
    int oc  = rem % 28;
    int tap = (rem / 28) % Kk;
    int c   = rem / (Kk * 28);
    const float* w = (l == 0) ? w0 : (l == 1) ? w1 : w2;
    wT[idx] = (oc < 27) ? w[((size_t)oc * Cc + c) * Kk + tap] : 0.f;
}

// ---------------------------------------------------------------------------
// Dynamic smem layout (bytes), total 59904, 2 CTAs/SM:
//   [0,     9216)   swgt float4[576]           (phase1: xs[16][120] at 0)
//   [9216,  18432)  sidx int4[576]             (phase1: wo spans 7680..23808)
//   [18432, 23040)  ssm float[1152]
//   [23040, 59904)  wsm[2][4608 floats]        (cp.async double buffer)
//   phase1 overlay: om[2][64][28] at 23808 (14336) — disjoint from swgt/sidx
// ---------------------------------------------------------------------------
#define SWGT_O  0
#define SIDX_O  9216
#define SSM_O   18432
#define WSM_O   23040
#define XS_O    0
#define WO_O    7680
#define OM_O    23808
#define SMEMSZ  59904

__global__ __launch_bounds__(256, 2) void dcn_fused_kernel(
    const float* __restrict__ x,
    const float* __restrict__ w_offT,  // [C][9][28]
    const float* __restrict__ b_off,   // [27]
    const float* __restrict__ wT,      // [C][9][O]
    const float* __restrict__ bias,    // [O]
    float* __restrict__ out)
{
    extern __shared__ __align__(16) char smem[];
    float4* swgt = (float4*)(smem + SWGT_O);
    int4*   sidx = (int4*)(smem + SIDX_O);

    int b   = blockIdx.y;
    int t   = blockIdx.x;             // 0..63
    int py0 = (t >> 3) * 8;
    int px0 = (t & 7) * 8;
    int tid = threadIdx.x;

    // ======================== Phase 1: offset conv ========================
    {
        float* xs_s = (float*)(smem + XS_O);           // [16][120]
        float* wo_s = (float*)(smem + WO_O);           // [16*252]
        float (*om_s)[64][28] = (float (*)[64][28])(smem + OM_O);

        int p   = tid & 63;
        int g   = tid >> 6;           // channel group 0..3
        int ppy = p >> 3;
        int ppx = p & 7;

        u64 aoff2[14];
#pragma unroll
        for (int j = 0; j < 14; j++) aoff2[j] = 0ull;

        float  hpf[8];
        float4 wpf[4];

        // prefetch round 0
        {
            const float4* wp4 = (const float4*)w_offT;
#pragma unroll
            for (int i8 = 0; i8 < 8; i8++) {
                int i = tid + 256 * i8;
                float v = 0.f;
                if (i < 1920) {
                    int ch  = i / 120;
                    int rem = i - ch * 120;
                    int rr  = rem / 12;
                    int cc2 = rem - rr * 12;
                    int gy  = py0 - 1 + rr;
                    int gx  = px0 - 1 + cc2;
                    if (cc2 < 10 && (unsigned)gy < (unsigned)Hh && (unsigned)gx < (unsigned)Ww)
                        v = __ldg(x + ((size_t)(b * Cc + ch)) * HW + gy * Ww + gx);
                }
                hpf[i8] = v;
            }
#pragma unroll
            for (int i4 = 0; i4 < 4; i4++) {
                int i = tid + 256 * i4;
                if (i < 1008) wpf[i4] = __ldg(wp4 + i);
            }
        }

        for (int r = 0; r < 16; r++) {
            __syncthreads();
#pragma unroll
            for (int i8 = 0; i8 < 8; i8++) {
                int i = tid + 256 * i8;
                if (i < 1920) {
                    int ch  = i / 120;
                    int rem = i - ch * 120;
                    xs_s[ch * 120 + rem] = hpf[i8];
                }
            }
            {
                float4* wo4 = (float4*)wo_s;
#pragma unroll
                for (int i4 = 0; i4 < 4; i4++) {
                    int i = tid + 256 * i4;
                    if (i < 1008) wo4[i] = wpf[i4];
                }
            }
            __syncthreads();

            if (r < 15) {
                int rn = r + 1;
                const float4* wp4 = (const float4*)(w_offT + (size_t)(rn << 4) * 252);
#pragma unroll
                for (int i8 = 0; i8 < 8; i8++) {
                    int i = tid + 256 * i8;
                    float v = 0.f;
                    if (i < 1920) {
                        int ch  = i / 120;
                        int rem = i - ch * 120;
                        int rr  = rem / 12;
                        int cc2 = rem - rr * 12;
                        int c   = (rn << 4) + ch;
                        int gy  = py0 - 1 + rr;
                        int gx  = px0 - 1 + cc2;
                        if (cc2 < 10 && (unsigned)gy < (unsigned)Hh && (unsigned)gx < (unsigned)Ww)
                            v = __ldg(x + ((size_t)(b * Cc + c)) * HW + gy * Ww + gx);
                    }
                    hpf[i8] = v;
                }
#pragma unroll
                for (int i4 = 0; i4 < 4; i4++) {
                    int i = tid + 256 * i4;
                    if (i < 1008) wpf[i4] = __ldg(wp4 + i);
                }
            }

#pragma unroll
            for (int ci = 0; ci < 4; ci++) {
                int ch = (g << 2) + ci;
                const float* xrow = xs_s + ch * 120;
                float xv[9];
#pragma unroll
                for (int rr = 0; rr < 3; rr++)
#pragma unroll
                    for (int cc = 0; cc < 3; cc++)
                        xv[rr * 3 + cc] = xrow[(ppy + rr) * 12 + ppx + cc];

#pragma unroll
                for (int tap = 0; tap < 9; tap++) {
                    u64 xt2 = pack2(xv[tap], xv[tap]);
                    const ulonglong2* wr = (const ulonglong2*)(wo_s + ch * 252 + tap * 28);
#pragma unroll
                    for (int j = 0; j < 7; j++) {
                        ulonglong2 wv2 = wr[j];
                        FMA2(aoff2[2 * j],     xt2, wv2.x);
                        FMA2(aoff2[2 * j + 1], xt2, wv2.y);
                    }
                }
            }
        }
        __syncthreads();
        // two-step cross-group reduction into om[2][64][28]
        if (g >= 2) {
#pragma unroll
            for (int j = 0; j < 14; j++)
                *(u64*)&om_s[g - 2][p][2 * j] = aoff2[j];
        }
        __syncthreads();
        if (g < 2) {
#pragma unroll
            for (int j = 0; j < 14; j++) {
                u64 tacc = *(u64*)&om_s[g][p][2 * j];
                ADDP2(tacc, aoff2[j]);
                *(u64*)&om_s[g][p][2 * j] = tacc;
            }
        }
        __syncthreads();

        // ---- Coordinate / gather-weight precompute (om disjoint from swgt) ----
        for (int i = tid; i < 576; i += 256) {
            int pp = i & 63;
            int k  = i >> 6;
            int gy = py0 + (pp >> 3);
            int gx = px0 + (pp & 7);
            float dy = __ldg(b_off + 2 * k)     + om_s[0][pp][2 * k]     + om_s[1][pp][2 * k];
            float dx = __ldg(b_off + 2 * k + 1) + om_s[0][pp][2 * k + 1] + om_s[1][pp][2 * k + 1];
            float mr = __ldg(b_off + 18 + k)    + om_s[0][pp][18 + k]    + om_s[1][pp][18 + k];
            float mv = 1.f / (1.f + expf(-mr));
            float ysv = (float)gy + (float)(k / 3 - 1) + dy;
            float xsv = (float)gx + (float)(k % 3 - 1) + dx;
            float y0f = floorf(ysv), x0f = floorf(xsv);
            float wy = ysv - y0f, wx = xsv - x0f;
            int y0 = (int)y0f, x0 = (int)x0f;
            int y1 = y0 + 1, x1 = x0 + 1;
            bool vy0 = (y0 >= 0) && (y0 < Hh);
            bool vy1 = (y1 >= 0) && (y1 < Hh);
            bool vx0 = (x0 >= 0) && (x0 < Ww);
            bool vx1 = (x1 >= 0) && (x1 < Ww);
            int y0c = min(max(y0, 0), Hh - 1), y1c = min(max(y1, 0), Hh - 1);
            int x0c = min(max(x0, 0), Ww - 1), x1c = min(max(x1, 0), Ww - 1);
            float4 wv;
            wv.x = (vy0 && vx0) ? mv * (1.f - wy) * (1.f - wx) : 0.f;
            wv.y = (vy0 && vx1) ? mv * (1.f - wy) * wx         : 0.f;
            wv.z = (vy1 && vx0) ? mv * wy * (1.f - wx)         : 0.f;
            wv.w = (vy1 && vx1) ? mv * wy * wx                 : 0.f;
            int4 iv;
            iv.x = y0c * Ww + x0c;
            iv.y = y0c * Ww + x1c;
            iv.z = y1c * Ww + x0c;
            iv.w = y1c * Ww + x1c;
            swgt[i] = wv;
            sidx[i] = iv;
        }
        __syncthreads();
    }

    // ================= Phase 2: sampling + GEMM + epilogue =================
    int to = tid >> 4;   // 0..15 -> o-base = to*16
    int tp = tid & 15;   // 0..15 -> p-base = tp*4

    u64 acc2[8][4];
#pragma unroll
    for (int i = 0; i < 8; i++)
#pragma unroll
        for (int j = 0; j < 4; j++) acc2[i][j] = 0ull;

    const float* xb = x + (size_t)b * Cc * HW;
    float* ssm = (float*)(smem + SSM_O);
    u32 wsm_base = smem_u32(smem + WSM_O);

    float pf[5][4];

    // prologue: cp.async chunk-0 weights into buf0; prefetch chunk-0 samples
    {
        const float4* wp4 = (const float4*)wT;
        u32 wdst = wsm_base + tid * 16;
#pragma unroll
        for (int q = 0; q < 5; q++) {
            int i = tid + 256 * q;
            if (q < 4 || tid < 128) CP_ASYNC16(wdst + q * 4096, wp4 + i);
        }
        CP_COMMIT();
#pragma unroll
        for (int q = 0; q < 5; q++) {
            int i = tid + 256 * q;
            if (q < 4 || tid < 128) {
                int cc = (i >= 576);
                int r  = i - (cc ? 576 : 0);
                int4 iv = sidx[r];
                const float* xp = xb + (size_t)cc * HW;
                pf[q][0] = __ldg(xp + iv.x);
                pf[q][1] = __ldg(xp + iv.y);
                pf[q][2] = __ldg(xp + iv.z);
                pf[q][3] = __ldg(xp + iv.w);
            }
        }
    }

    for (int c0 = 0; c0 < Cc; c0 += 2) {
        int s = (c0 >> 1) & 1;
        // commit prefetched samples (combine + STS) for this chunk
#pragma unroll
        for (int q = 0; q < 5; q++) {
            int i = tid + 256 * q;
            if (q < 4 || tid < 128) {
                int cc = (i >= 576);
                int r  = i - (cc ? 576 : 0);
                float4 wv = swgt[r];
                ssm[i] = wv.x * pf[q][0] + wv.y * pf[q][1]
                       + wv.z * pf[q][2] + wv.w * pf[q][3];
            }
        }
        CP_WAIT0();          // this chunk's weights have landed (issued last iter)
        __syncthreads();     // barrier1: ssm + wsm[s] visible to all

        // issue next chunk's weight cp.async (into idle buffer) + sample prefetch
        if (c0 + 2 < Cc) {
            const float4* wp4 = (const float4*)(wT + (size_t)(c0 + 2) * 2304);
            u32 wdst = wsm_base + (s ^ 1) * 18432 + tid * 16;
#pragma unroll
            for (int q = 0; q < 5; q++) {
                int i = tid + 256 * q;
                if (q < 4 || tid < 128) CP_ASYNC16(wdst + q * 4096, wp4 + i);
            }
            CP_COMMIT();
            const float* xn = xb + (size_t)(c0 + 2) * HW;
#pragma unroll
            for (int q = 0; q < 5; q++) {
                int i = tid + 256 * q;
                if (q < 4 || tid < 128) {
                    int cc = (i >= 576);
                    int r  = i - (cc ? 576 : 0);
                    int4 iv = sidx[r];
                    const float* xp = xn + (size_t)cc * HW;
                    pf[q][0] = __ldg(xp + iv.x);
                    pf[q][1] = __ldg(xp + iv.y);
                    pf[q][2] = __ldg(xp + iv.z);
                    pf[q][3] = __ldg(xp + iv.w);
                }
            }
        }

        const float* wsm = (const float*)(smem + WSM_O + s * 18432);
#pragma unroll
        for (int cc = 0; cc < 2; cc++) {
#pragma unroll
            for (int k = 0; k < 9; k++) {
                const float* wr = wsm + cc * 2304 + k * 256 + (to << 4);
                ulonglong2 w01 = *(const ulonglong2*)(wr);
                ulonglong2 w23 = *(const ulonglong2*)(wr + 4);
                ulonglong2 w45 = *(const ulonglong2*)(wr + 8);
                ulonglong2 w67 = *(const ulonglong2*)(wr + 12);
                float4 sv = *(const float4*)(ssm + cc * 576 + k * 64 + (tp << 2));
                u64 sp[4];
                sp[0] = pack2(sv.x, sv.x);
                sp[1] = pack2(sv.y, sv.y);
                sp[2] = pack2(sv.z, sv.z);
                sp[3] = pack2(sv.w, sv.w);
                u64 wp[8] = {w01.x, w01.y, w23.x, w23.y, w45.x, w45.y, w67.x, w67.y};
#pragma unroll
                for (int op = 0; op < 8; op++)
#pragma unroll
                    for (int jj = 0; jj < 4; jj++)
                        FMA2(acc2[op][jj], wp[op], sp[jj]);
            }
        }
        __syncthreads();     // barrier2: everyone done reading ssm + wsm[s]
    }

    // epilogue: bias + ReLU, vectorized stores
    {
        int row = tp >> 1;
        int cb  = (tp & 1) << 2;
#pragma unroll
        for (int op = 0; op < 8; op++) {
            int o0 = (to << 4) + (op << 1);
            float bv0 = __ldg(bias + o0);
            float bv1 = __ldg(bias + o0 + 1);
            float2 v0 = unpack2(acc2[op][0]);
            float2 v1 = unpack2(acc2[op][1]);
            float2 v2 = unpack2(acc2[op][2]);
            float2 v3 = unpack2(acc2[op][3]);
            float4 lo, hi;
            lo.x = fmaxf(v0.x + bv0, 0.f); lo.y = fmaxf(v1.x + bv0, 0.f);
            lo.z = fmaxf(v2.x + bv0, 0.f); lo.w = fmaxf(v3.x + bv0, 0.f);
            hi.x = fmaxf(v0.y + bv1, 0.f); hi.y = fmaxf(v1.y + bv1, 0.f);
            hi.z = fmaxf(v2.y + bv1, 0.f); hi.w = fmaxf(v3.y + bv1, 0.f);
            size_t base0 = ((size_t)(b * Onc + o0) * Hh + py0 + row) * Ww + px0 + cb;
            size_t base1 = base0 + (size_t)Hh * Ww;
            *(float4*)(out + base0) = lo;
            *(float4*)(out + base1) = hi;
        }
    }
}

// ---------------------------------------------------------------------------
// Launch
// ---------------------------------------------------------------------------
extern "C" void kernel_launch(void* const* d_in, const int* in_sizes, int n_in,
                              void* d_out, int out_size)
{
    const float* x = (const float*)d_in[0];
    const float* w_off[3] = {(const float*)d_in[1], (const float*)d_in[5], (const float*)d_in[9]};
    const float* b_off[3] = {(const float*)d_in[2], (const float*)d_in[6], (const float*)d_in[10]};
    const float* wq[3]    = {(const float*)d_in[3], (const float*)d_in[7], (const float*)d_in[11]};
    const float* bias[3]  = {(const float*)d_in[4], (const float*)d_in[8], (const float*)d_in[12]};

    float *buf1, *buf2, *wT, *woT;
    cudaGetSymbolAddress((void**)&buf1, g_buf1);
    cudaGetSymbolAddress((void**)&buf2, g_buf2);
    cudaGetSymbolAddress((void**)&wT, g_wT);
    cudaGetSymbolAddress((void**)&woT, g_woT);

    cudaFuncSetAttribute(dcn_fused_kernel, cudaFuncAttributeMaxDynamicSharedMemorySize, SMEMSZ);

    transpose_w_all<<<(3 * Cc * Kk * Onc + 255) / 256, 256>>>(wq[0], wq[1], wq[2], wT);
    transpose_woff_all<<<(3 * Cc * Kk * 28 + 255) / 256, 256>>>(w_off[0], w_off[1], w_off[2], woT);

    const float* src[3] = {x, buf1, buf2};
    float*       dst[3] = {buf1, buf2, (float*)d_out};

    for (int l = 0; l < 3; l++) {
        dcn_fused_kernel<<<dim3(64, Bn), 256, SMEMSZ>>>(src[l],
                                                        woT + (size_t)l * Cc * Kk * 28,
                                                        b_off[l],
                                                        wT + (size_t)l * Cc * Kk * Onc,
                                                        bias[l], dst[l]);
    }
}

// round 13
// speedup vs baseline: 1.2735x; 1.0319x over previous
#include <cuda_runtime.h>
#include <math.h>
#include <cstdint>

#define Bn 4
#define Cc 256
#define Onc 256
#define Hh 64
#define Ww 64
#define Kk 9
#define HW 4096
#define NT 128            // threads per CTA
#define NPX 32            // pixels per tile (4 rows x 8 cols)
#define NS 288            // samples per channel (9 taps x 32 px)

typedef unsigned long long u64;
typedef uint32_t u32;

// Scratch (static device arrays — no allocation)
__device__ float g_buf1[Bn * Cc * HW];
__device__ float g_buf2[Bn * Cc * HW];
__device__ float g_wT[3 * Cc * Kk * Onc];       // main weights [l][c][k][o]
__device__ float g_woT[3 * Cc * Kk * 28];       // offset weights [l][c][tap][28]

// ---- packed f32x2 helpers -------------------------------------------------
#define FMA2(d, a, b)  asm("fma.rn.f32x2 %0, %1, %2, %0;" : "+l"(d) : "l"(a), "l"(b))
#define ADDP2(d, a)    asm("add.rn.f32x2 %0, %1, %0;" : "+l"(d) : "l"(a))

__device__ __forceinline__ u64 pack2(float lo, float hi) {
    u64 r; asm("mov.b64 %0, {%1,%2};" : "=l"(r) : "f"(lo), "f"(hi)); return r;
}
__device__ __forceinline__ float2 unpack2(u64 v) {
    float2 f; asm("mov.b64 {%0,%1}, %2;" : "=f"(f.x), "=f"(f.y) : "l"(v)); return f;
}

// ---- cp.async helpers -----------------------------------------------------
__device__ __forceinline__ u32 smem_u32(const void* p) {
    u32 a;
    asm("{ .reg .u64 t; cvta.to.shared.u64 t, %1; cvt.u32.u64 %0, t; }" : "=r"(a) : "l"(p));
    return a;
}
#define CP_ASYNC16(dst, src) \
    asm volatile("cp.async.cg.shared.global [%0], [%1], 16;" :: "r"(dst), "l"(src))
#define CP_COMMIT() asm volatile("cp.async.commit_group;" ::: "memory")
#define CP_WAIT0()  asm volatile("cp.async.wait_group 0;" ::: "memory")

// ---------------------------------------------------------------------------
// Prep (merged over 3 layers)
// ---------------------------------------------------------------------------
__global__ void transpose_w_all(const float* __restrict__ w0, const float* __restrict__ w1,
                                const float* __restrict__ w2, float* __restrict__ wT)
{
    int idx = blockIdx.x * blockDim.x + threadIdx.x;
    if (idx >= 3 * Cc * Kk * Onc) return;
    int l   = idx / (Cc * Kk * Onc);
    int rem = idx - l * (Cc * Kk * Onc);
    int o = rem & (Onc - 1);
    int k = (rem >> 8) % Kk;
    int c = rem / (Kk * Onc);
    const float* w = (l == 0) ? w0 : (l == 1) ? w1 : w2;
    wT[idx] = w[((size_t)o * Cc + c) * Kk + k];
}

__global__ void transpose_woff_all(const float* __restrict__ w0, const float* __restrict__ w1,
                                   const float* __restrict__ w2, float* __restrict__ wT)
{
    int idx = blockIdx.x * blockDim.x + threadIdx.x;
    if (idx >= 3 * Cc * Kk * 28) return;
    int l   = idx / (Cc * Kk * 28);
    int rem = idx - l * (Cc * Kk * 28);
    int oc  = rem % 28;
    int tap = (rem / 28) % Kk;
    int c   = rem / (Kk * 28);
    const float* w = (l == 0) ? w0 : (l == 1) ? w1 : w2;
    wT[idx] = (oc < 27) ? w[((size_t)oc * Cc + c) * Kk + tap] : 0.f;
}

// ---------------------------------------------------------------------------
// Dynamic smem layout (bytes), total 48384, 4 CTAs/SM:
//   [0,     4608)   swgt float4[288]
//   [4608,  9216)   sidx int4[288]
//   [9216,  11520)  ssm float[576]
//   [11520, 48384)  wsm[2][4608 floats]   (cp.async double buffer)
// Phase-1 overlays: xs[16][72] at 0 (4608) + wo[16*252] at 4608 (16128 -> 20736);
//                   om[2][32][28] at 20736 (7168) — disjoint.
// ---------------------------------------------------------------------------
#define SWGT_O  0
#define SIDX_O  4608
#define SSM_O   9216
#define WSM_O   11520
#define XS_O    0
#define WO_O    4608
#define OM_O    20736
#define SMEMSZ  48384

__global__ __launch_bounds__(NT, 4) void dcn_fused_kernel(
    const float* __restrict__ x,
    const float* __restrict__ w_offT,  // [C][9][28]
    const float* __restrict__ b_off,   // [27]
    const float* __restrict__ wT,      // [C][9][O]
    const float* __restrict__ bias,    // [O]
    float* __restrict__ out)
{
    extern __shared__ __align__(16) char smem[];
    float4* swgt = (float4*)(smem + SWGT_O);
    int4*   sidx = (int4*)(smem + SIDX_O);

    int b   = blockIdx.y;
    int t   = blockIdx.x;             // 0..127
    int py0 = (t >> 3) * 4;           // 16 tile-rows of 4
    int px0 = (t & 7) * 8;            // 8 tile-cols of 8
    int tid = threadIdx.x;

    // ======================== Phase 1: offset conv ========================
    {
        float* xs_s = (float*)(smem + XS_O);           // [16][72] (6x12 halo)
        float* wo_s = (float*)(smem + WO_O);           // [16*252]
        float (*om_s)[NPX][28] = (float (*)[NPX][28])(smem + OM_O);

        int p   = tid & 31;
        int g   = tid >> 5;           // channel group 0..3
        int ppy = p >> 3;             // 0..3
        int ppx = p & 7;

        u64 aoff2[14];
#pragma unroll
        for (int j = 0; j < 14; j++) aoff2[j] = 0ull;

        float  hpf[9];
        float4 wpf[8];

        // prefetch round 0
        {
            const float4* wp4 = (const float4*)w_offT;
#pragma unroll
            for (int i9 = 0; i9 < 9; i9++) {
                int i = tid + NT * i9;       // 0..1151
                int ch  = i / 72;
                int rem = i - ch * 72;
                int rr  = rem / 12;
                int cc2 = rem - rr * 12;
                int gy  = py0 - 1 + rr;
                int gx  = px0 - 1 + cc2;
                float v = 0.f;
                if (cc2 < 10 && (unsigned)gy < (unsigned)Hh && (unsigned)gx < (unsigned)Ww)
                    v = __ldg(x + ((size_t)(b * Cc + ch)) * HW + gy * Ww + gx);
                hpf[i9] = v;
            }
#pragma unroll
            for (int i8 = 0; i8 < 8; i8++) {
                int i = tid + NT * i8;
                if (i < 1008) wpf[i8] = __ldg(wp4 + i);
            }
        }

        for (int r = 0; r < 16; r++) {
            __syncthreads();
#pragma unroll
            for (int i9 = 0; i9 < 9; i9++) {
                int i = tid + NT * i9;
                xs_s[i] = hpf[i9];
            }
            {
                float4* wo4 = (float4*)wo_s;
#pragma unroll
                for (int i8 = 0; i8 < 8; i8++) {
                    int i = tid + NT * i8;
                    if (i < 1008) wo4[i] = wpf[i8];
                }
            }
            __syncthreads();

            if (r < 15) {
                int rn = r + 1;
                const float4* wp4 = (const float4*)(w_offT + (size_t)(rn << 4) * 252);
#pragma unroll
                for (int i9 = 0; i9 < 9; i9++) {
                    int i = tid + NT * i9;
                    int ch  = i / 72;
                    int rem = i - ch * 72;
                    int rr  = rem / 12;
                    int cc2 = rem - rr * 12;
                    int c   = (rn << 4) + ch;
                    int gy  = py0 - 1 + rr;
                    int gx  = px0 - 1 + cc2;
                    float v = 0.f;
                    if (cc2 < 10 && (unsigned)gy < (unsigned)Hh && (unsigned)gx < (unsigned)Ww)
                        v = __ldg(x + ((size_t)(b * Cc + c)) * HW + gy * Ww + gx);
                    hpf[i9] = v;
                }
#pragma unroll
                for (int i8 = 0; i8 < 8; i8++) {
                    int i = tid + NT * i8;
                    if (i < 1008) wpf[i8] = __ldg(wp4 + i);
                }
            }

#pragma unroll
            for (int ci = 0; ci < 4; ci++) {
                int ch = (g << 2) + ci;
                const float* xrow = xs_s + ch * 72;
                float xv[9];
#pragma unroll
                for (int rr = 0; rr < 3; rr++)
#pragma unroll
                    for (int cc = 0; cc < 3; cc++)
                        xv[rr * 3 + cc] = xrow[(ppy + rr) * 12 + ppx + cc];

#pragma unroll
                for (int tap = 0; tap < 9; tap++) {
                    u64 xt2 = pack2(xv[tap], xv[tap]);
                    const ulonglong2* wr = (const ulonglong2*)(wo_s + ch * 252 + tap * 28);
#pragma unroll
                    for (int j = 0; j < 7; j++) {
                        ulonglong2 wv2 = wr[j];
                        FMA2(aoff2[2 * j],     xt2, wv2.x);
                        FMA2(aoff2[2 * j + 1], xt2, wv2.y);
                    }
                }
            }
        }
        __syncthreads();
        // two-step cross-group reduction into om[2][32][28]
        if (g >= 2) {
#pragma unroll
            for (int j = 0; j < 14; j++)
                *(u64*)&om_s[g - 2][p][2 * j] = aoff2[j];
        }
        __syncthreads();
        if (g < 2) {
#pragma unroll
            for (int j = 0; j < 14; j++) {
                u64 tacc = *(u64*)&om_s[g][p][2 * j];
                ADDP2(tacc, aoff2[j]);
                *(u64*)&om_s[g][p][2 * j] = tacc;
            }
        }
        __syncthreads();

        // ---- Coordinate / gather-weight precompute ----
        for (int i = tid; i < NS; i += NT) {
            int pp = i & 31;
            int k  = i >> 5;
            int gy = py0 + (pp >> 3);
            int gx = px0 + (pp & 7);
            float dy = __ldg(b_off + 2 * k)     + om_s[0][pp][2 * k]     + om_s[1][pp][2 * k];
            float dx = __ldg(b_off + 2 * k + 1) + om_s[0][pp][2 * k + 1] + om_s[1][pp][2 * k + 1];
            float mr = __ldg(b_off + 18 + k)    + om_s[0][pp][18 + k]    + om_s[1][pp][18 + k];
            float mv = 1.f / (1.f + expf(-mr));
            float ysv = (float)gy + (float)(k / 3 - 1) + dy;
            float xsv = (float)gx + (float)(k % 3 - 1) + dx;
            float y0f = floorf(ysv), x0f = floorf(xsv);
            float wy = ysv - y0f, wx = xsv - x0f;
            int y0 = (int)y0f, x0 = (int)x0f;
            int y1 = y0 + 1, x1 = x0 + 1;
            bool vy0 = (y0 >= 0) && (y0 < Hh);
            bool vy1 = (y1 >= 0) && (y1 < Hh);
            bool vx0 = (x0 >= 0) && (x0 < Ww);
            bool vx1 = (x1 >= 0) && (x1 < Ww);
            int y0c = min(max(y0, 0), Hh - 1), y1c = min(max(y1, 0), Hh - 1);
            int x0c = min(max(x0, 0), Ww - 1), x1c = min(max(x1, 0), Ww - 1);
            float4 wv;
            wv.x = (vy0 && vx0) ? mv * (1.f - wy) * (1.f - wx) : 0.f;
            wv.y = (vy0 && vx1) ? mv * (1.f - wy) * wx         : 0.f;
            wv.z = (vy1 && vx0) ? mv * wy * (1.f - wx)         : 0.f;
            wv.w = (vy1 && vx1) ? mv * wy * wx                 : 0.f;
            int4 iv;
            iv.x = y0c * Ww + x0c;
            iv.y = y0c * Ww + x1c;
            iv.z = y1c * Ww + x0c;
            iv.w = y1c * Ww + x1c;
            swgt[i] = wv;
            sidx[i] = iv;
        }
        __syncthreads();
    }

    // ================= Phase 2: sampling + GEMM + epilogue =================
    int to = tid >> 3;   // 0..15 -> o-base = to*16
    int tp = tid & 7;    // 0..7  -> p-base = tp*4

    u64 acc2[8][4];
#pragma unroll
    for (int i = 0; i < 8; i++)
#pragma unroll
        for (int j = 0; j < 4; j++) acc2[i][j] = 0ull;

    const float* xb = x + (size_t)b * Cc * HW;
    float* ssm = (float*)(smem + SSM_O);
    u32 wsm_base = smem_u32(smem + WSM_O);

    float pf[5][4];

    // prologue: cp.async chunk-0 weights into buf0; prefetch chunk-0 samples
    {
        const float4* wp4 = (const float4*)wT;
        u32 wdst = wsm_base + tid * 16;
#pragma unroll
        for (int q = 0; q < 9; q++)
            CP_ASYNC16(wdst + q * 2048, wp4 + tid + NT * q);
        CP_COMMIT();
#pragma unroll
        for (int q = 0; q < 5; q++) {
            int i = tid + NT * q;
            if (q < 4 || tid < 64) {
                int cc = (i >= NS);
                int r  = i - (cc ? NS : 0);
                int4 iv = sidx[r];
                const float* xp = xb + (size_t)cc * HW;
                pf[q][0] = __ldg(xp + iv.x);
                pf[q][1] = __ldg(xp + iv.y);
                pf[q][2] = __ldg(xp + iv.z);
                pf[q][3] = __ldg(xp + iv.w);
            }
        }
    }

    for (int c0 = 0; c0 < Cc; c0 += 2) {
        int s = (c0 >> 1) & 1;
        // commit prefetched samples (combine + STS) for this chunk
#pragma unroll
        for (int q = 0; q < 5; q++) {
            int i = tid + NT * q;
            if (q < 4 || tid < 64) {
                int cc = (i >= NS);
                int r  = i - (cc ? NS : 0);
                float4 wv = swgt[r];
                ssm[i] = wv.x * pf[q][0] + wv.y * pf[q][1]
                       + wv.z * pf[q][2] + wv.w * pf[q][3];
            }
        }
        CP_WAIT0();          // this chunk's weights have landed
        __syncthreads();     // barrier1: ssm + wsm[s] visible to all

        // issue next chunk's weight cp.async + sample prefetch (overlap GEMM)
        if (c0 + 2 < Cc) {
            const float4* wp4 = (const float4*)(wT + (size_t)(c0 + 2) * 2304);
            u32 wdst = wsm_base + (s ^ 1) * 18432 + tid * 16;
#pragma unroll
            for (int q = 0; q < 9; q++)
                CP_ASYNC16(wdst + q * 2048, wp4 + tid + NT * q);
            CP_COMMIT();
            const float* xn = xb + (size_t)(c0 + 2) * HW;
#pragma unroll
            for (int q = 0; q < 5; q++) {
                int i = tid + NT * q;
                if (q < 4 || tid < 64) {
                    int cc = (i >= NS);
                    int r  = i - (cc ? NS : 0);
                    int4 iv = sidx[r];
                    const float* xp = xn + (size_t)cc * HW;
                    pf[q][0] = __ldg(xp + iv.x);
                    pf[q][1] = __ldg(xp + iv.y);
                    pf[q][2] = __ldg(xp + iv.z);
                    pf[q][3] = __ldg(xp + iv.w);
                }
            }
        }

        const float* wsm = (const float*)(smem + WSM_O + s * 18432);
#pragma unroll
        for (int cc = 0; cc < 2; cc++) {
#pragma unroll
            for (int k = 0; k < 9; k++) {
                const float* wr = wsm + cc * 2304 + k * 256 + (to << 4);
                ulonglong2 w01 = *(const ulonglong2*)(wr);
                ulonglong2 w23 = *(const ulonglong2*)(wr + 4);
                ulonglong2 w45 = *(const ulonglong2*)(wr + 8);
                ulonglong2 w67 = *(const ulonglong2*)(wr + 12);
                float4 sv = *(const float4*)(ssm + cc * NS + k * NPX + (tp << 2));
                u64 sp[4];
                sp[0] = pack2(sv.x, sv.x);
                sp[1] = pack2(sv.y, sv.y);
                sp[2] = pack2(sv.z, sv.z);
                sp[3] = pack2(sv.w, sv.w);
                u64 wp[8] = {w01.x, w01.y, w23.x, w23.y, w45.x, w45.y, w67.x, w67.y};
#pragma unroll
                for (int op = 0; op < 8; op++)
#pragma unroll
                    for (int jj = 0; jj < 4; jj++)
                        FMA2(acc2[op][jj], wp[op], sp[jj]);
            }
        }
        __syncthreads();     // barrier2: all done reading ssm + wsm[s]
    }

    // epilogue: bias + ReLU, vectorized stores
    {
        int row = tp >> 1;               // 0..3
        int cb  = (tp & 1) << 2;         // 0 or 4
#pragma unroll
        for (int op = 0; op < 8; op++) {
            int o0 = (to << 4) + (op << 1);
            float bv0 = __ldg(bias + o0);
            float bv1 = __ldg(bias + o0 + 1);
            float2 v0 = unpack2(acc2[op][0]);
            float2 v1 = unpack2(acc2[op][1]);
            float2 v2 = unpack2(acc2[op][2]);
            float2 v3 = unpack2(acc2[op][3]);
            float4 lo, hi;
            lo.x = fmaxf(v0.x + bv0, 0.f); lo.y = fmaxf(v1.x + bv0, 0.f);
            lo.z = fmaxf(v2.x + bv0, 0.f); lo.w = fmaxf(v3.x + bv0, 0.f);
            hi.x = fmaxf(v0.y + bv1, 0.f); hi.y = fmaxf(v1.y + bv1, 0.f);
            hi.z = fmaxf(v2.y + bv1, 0.f); hi.w = fmaxf(v3.y + bv1, 0.f);
            size_t base0 = ((size_t)(b * Onc + o0) * Hh + py0 + row) * Ww + px0 + cb;
            size_t base1 = base0 + (size_t)Hh * Ww;
            *(float4*)(out + base0) = lo;
            *(float4*)(out + base1) = hi;
        }
    }
}

// ---------------------------------------------------------------------------
// Launch
// ---------------------------------------------------------------------------
extern "C" void kernel_launch(void* const* d_in, const int* in_sizes, int n_in,
                              void* d_out, int out_size)
{
    const float* x = (const float*)d_in[0];
    const float* w_off[3] = {(const float*)d_in[1], (const float*)d_in[5], (const float*)d_in[9]};
    const float* b_off[3] = {(const float*)d_in[2], (const float*)d_in[6], (const float*)d_in[10]};
    const float* wq[3]    = {(const float*)d_in[3], (const float*)d_in[7], (const float*)d_in[11]};
    const float* bias[3]  = {(const float*)d_in[4], (const float*)d_in[8], (const float*)d_in[12]};

    float *buf1, *buf2, *wT, *woT;
    cudaGetSymbolAddress((void**)&buf1, g_buf1);
    cudaGetSymbolAddress((void**)&buf2, g_buf2);
    cudaGetSymbolAddress((void**)&wT, g_wT);
    cudaGetSymbolAddress((void**)&woT, g_woT);

    cudaFuncSetAttribute(dcn_fused_kernel, cudaFuncAttributeMaxDynamicSharedMemorySize, SMEMSZ);

    transpose_w_all<<<(3 * Cc * Kk * Onc + 255) / 256, 256>>>(wq[0], wq[1], wq[2], wT);
    transpose_woff_all<<<(3 * Cc * Kk * 28 + 255) / 256, 256>>>(w_off[0], w_off[1], w_off[2], woT);

    const float* src[3] = {x, buf1, buf2};
    float*       dst[3] = {buf1, buf2, (float*)d_out};

    for (int l = 0; l < 3; l++) {
        dcn_fused_kernel<<<dim3(128, Bn), NT, SMEMSZ>>>(src[l],
                                                        woT + (size_t)l * Cc * Kk * 28,
                                                        b_off[l],
                                                        wT + (size_t)l * Cc * Kk * Onc,
                                                        bias[l], dst[l]);
    }
}

// round 14
// speedup vs baseline: 1.2783x; 1.0038x over previous
#include <cuda_runtime.h>
#include <math.h>
#include <cstdint>

#define Bn 4
#define Cc 256
#define Onc 256
#define Hh 64
#define Ww 64
#define Kk 9
#define HW 4096
#define NT 128            // threads per CTA
#define NPX 32            // pixels per tile (4 rows x 8 cols)
#define NS 288            // samples per channel (9 taps x 32 px)

typedef unsigned long long u64;
typedef uint32_t u32;

// Scratch (static device arrays — no allocation)
__device__ float g_buf1[Bn * Cc * HW];
__device__ float g_buf2[Bn * Cc * HW];
__device__ float g_wT[3 * Cc * Kk * Onc];       // main weights [l][c][k][o]
__device__ float g_woT[3 * Cc * Kk * 28];       // offset weights [l][c][tap][28]

// ---- packed f32x2 helpers -------------------------------------------------
#define FMA2(d, a, b)  asm("fma.rn.f32x2 %0, %1, %2, %0;" : "+l"(d) : "l"(a), "l"(b))
#define ADDP2(d, a)    asm("add.rn.f32x2 %0, %1, %0;" : "+l"(d) : "l"(a))

__device__ __forceinline__ u64 pack2(float lo, float hi) {
    u64 r; asm("mov.b64 %0, {%1,%2};" : "=l"(r) : "f"(lo), "f"(hi)); return r;
}
__device__ __forceinline__ float2 unpack2(u64 v) {
    float2 f; asm("mov.b64 {%0,%1}, %2;" : "=f"(f.x), "=f"(f.y) : "l"(v)); return f;
}

// ---- cp.async helpers -----------------------------------------------------
__device__ __forceinline__ u32 smem_u32(const void* p) {
    u32 a;
    asm("{ .reg .u64 t; cvta.to.shared.u64 t, %1; cvt.u32.u64 %0, t; }" : "=r"(a) : "l"(p));
    return a;
}
#define CP_ASYNC16(dst, src) \
    asm volatile("cp.async.cg.shared.global [%0], [%1], 16;" :: "r"(dst), "l"(src))
#define CP_COMMIT() asm volatile("cp.async.commit_group;" ::: "memory")
#define CP_WAIT0()  asm volatile("cp.async.wait_group 0;" ::: "memory")

// ---------------------------------------------------------------------------
// Prep (merged over 3 layers)
// ---------------------------------------------------------------------------
__global__ void transpose_w_all(const float* __restrict__ w0, const float* __restrict__ w1,
                                const float* __restrict__ w2, float* __restrict__ wT)
{
    int idx = blockIdx.x * blockDim.x + threadIdx.x;
    if (idx >= 3 * Cc * Kk * Onc) return;
    int l   = idx / (Cc * Kk * Onc);
    int rem = idx - l * (Cc * Kk * Onc);
    int o = rem & (Onc - 1);
    int k = (rem >> 8) % Kk;
    int c = rem / (Kk * Onc);
    const float* w = (l == 0) ? w0 : (l == 1) ? w1 : w2;
    wT[idx] = w[((size_t)o * Cc + c) * Kk + k];
}

__global__ void transpose_woff_all(const float* __restrict__ w0, const float* __restrict__ w1,
                                   const float* __restrict__ w2, float* __restrict__ wT)
{
    int idx = blockIdx.x * blockDim.x + threadIdx.x;
    if (idx >= 3 * Cc * Kk * 28) return;
    int l   = idx / (Cc * Kk * 28);
    int rem = idx - l * (Cc * Kk * 28);
    int oc  = rem % 28;
    int tap = (rem / 28) % Kk;
    int c   = rem / (Kk * 28);
    const float* w = (l == 0) ? w0 : (l == 1) ? w1 : w2;
    wT[idx] = (oc < 27) ? w[((size_t)oc * Cc + c) * Kk + tap] : 0.f;
}

// ---------------------------------------------------------------------------
// Dynamic smem layout (bytes), total 50688, 4 CTAs/SM:
//   [0,     4608)   swgt float4[288]
//   [4608,  9216)   sidx int4[288]
//   [9216,  13824)  ssm[2][576 floats]    (double-buffered samples)
//   [13824, 50688)  wsm[2][4608 floats]   (cp.async double buffer)
// Phase-1 overlays: xs[16][72] at 0 (4608) + wo[16*252] at 4608 (-> 20736);
//                   om[2][32][28] at 20736 (7168) — disjoint.
// ---------------------------------------------------------------------------
#define SWGT_O  0
#define SIDX_O  4608
#define SSM_O   9216
#define WSM_O   13824
#define XS_O    0
#define WO_O    4608
#define OM_O    20736
#define SMEMSZ  50688

__global__ __launch_bounds__(NT, 4) void dcn_fused_kernel(
    const float* __restrict__ x,
    const float* __restrict__ w_offT,  // [C][9][28]
    const float* __restrict__ b_off,   // [27]
    const float* __restrict__ wT,      // [C][9][O]
    const float* __restrict__ bias,    // [O]
    float* __restrict__ out)
{
    extern __shared__ __align__(16) char smem[];
    float4* swgt = (float4*)(smem + SWGT_O);
    int4*   sidx = (int4*)(smem + SIDX_O);

    int b   = blockIdx.y;
    int t   = blockIdx.x;             // 0..127
    int py0 = (t >> 3) * 4;           // 16 tile-rows of 4
    int px0 = (t & 7) * 8;            // 8 tile-cols of 8
    int tid = threadIdx.x;

    // ======================== Phase 1: offset conv ========================
    {
        float* xs_s = (float*)(smem + XS_O);           // [16][72] (6x12 halo)
        float* wo_s = (float*)(smem + WO_O);           // [16*252]
        float (*om_s)[NPX][28] = (float (*)[NPX][28])(smem + OM_O);

        int p   = tid & 31;
        int g   = tid >> 5;           // channel group 0..3
        int ppy = p >> 3;             // 0..3
        int ppx = p & 7;

        u64 aoff2[14];
#pragma unroll
        for (int j = 0; j < 14; j++) aoff2[j] = 0ull;

        float  hpf[9];
        float4 wpf[8];

        // prefetch round 0
        {
            const float4* wp4 = (const float4*)w_offT;
#pragma unroll
            for (int i9 = 0; i9 < 9; i9++) {
                int i = tid + NT * i9;       // 0..1151
                int ch  = i / 72;
                int rem = i - ch * 72;
                int rr  = rem / 12;
                int cc2 = rem - rr * 12;
                int gy  = py0 - 1 + rr;
                int gx  = px0 - 1 + cc2;
                float v = 0.f;
                if (cc2 < 10 && (unsigned)gy < (unsigned)Hh && (unsigned)gx < (unsigned)Ww)
                    v = __ldg(x + ((size_t)(b * Cc + ch)) * HW + gy * Ww + gx);
                hpf[i9] = v;
            }
#pragma unroll
            for (int i8 = 0; i8 < 8; i8++) {
                int i = tid + NT * i8;
                if (i < 1008) wpf[i8] = __ldg(wp4 + i);
            }
        }

        for (int r = 0; r < 16; r++) {
            __syncthreads();
#pragma unroll
            for (int i9 = 0; i9 < 9; i9++) {
                int i = tid + NT * i9;
                xs_s[i] = hpf[i9];
            }
            {
                float4* wo4 = (float4*)wo_s;
#pragma unroll
                for (int i8 = 0; i8 < 8; i8++) {
                    int i = tid + NT * i8;
                    if (i < 1008) wo4[i] = wpf[i8];
                }
            }
            __syncthreads();

            if (r < 15) {
                int rn = r + 1;
                const float4* wp4 = (const float4*)(w_offT + (size_t)(rn << 4) * 252);
#pragma unroll
                for (int i9 = 0; i9 < 9; i9++) {
                    int i = tid + NT * i9;
                    int ch  = i / 72;
                    int rem = i - ch * 72;
                    int rr  = rem / 12;
                    int cc2 = rem - rr * 12;
                    int c   = (rn << 4) + ch;
                    int gy  = py0 - 1 + rr;
                    int gx  = px0 - 1 + cc2;
                    float v = 0.f;
                    if (cc2 < 10 && (unsigned)gy < (unsigned)Hh && (unsigned)gx < (unsigned)Ww)
                        v = __ldg(x + ((size_t)(b * Cc + c)) * HW + gy * Ww + gx);
                    hpf[i9] = v;
                }
#pragma unroll
                for (int i8 = 0; i8 < 8; i8++) {
                    int i = tid + NT * i8;
                    if (i < 1008) wpf[i8] = __ldg(wp4 + i);
                }
            }

#pragma unroll
            for (int ci = 0; ci < 4; ci++) {
                int ch = (g << 2) + ci;
                const float* xrow = xs_s + ch * 72;
                float xv[9];
#pragma unroll
                for (int rr = 0; rr < 3; rr++)
#pragma unroll
                    for (int cc = 0; cc < 3; cc++)
                        xv[rr * 3 + cc] = xrow[(ppy + rr) * 12 + ppx + cc];

#pragma unroll
                for (int tap = 0; tap < 9; tap++) {
                    u64 xt2 = pack2(xv[tap], xv[tap]);
                    const ulonglong2* wr = (const ulonglong2*)(wo_s + ch * 252 + tap * 28);
#pragma unroll
                    for (int j = 0; j < 7; j++) {
                        ulonglong2 wv2 = wr[j];
                        FMA2(aoff2[2 * j],     xt2, wv2.x);
                        FMA2(aoff2[2 * j + 1], xt2, wv2.y);
                    }
                }
            }
        }
        __syncthreads();
        // two-step cross-group reduction into om[2][32][28]
        if (g >= 2) {
#pragma unroll
            for (int j = 0; j < 14; j++)
                *(u64*)&om_s[g - 2][p][2 * j] = aoff2[j];
        }
        __syncthreads();
        if (g < 2) {
#pragma unroll
            for (int j = 0; j < 14; j++) {
                u64 tacc = *(u64*)&om_s[g][p][2 * j];
                ADDP2(tacc, aoff2[j]);
                *(u64*)&om_s[g][p][2 * j] = tacc;
            }
        }
        __syncthreads();

        // ---- Coordinate / gather-weight precompute ----
        for (int i = tid; i < NS; i += NT) {
            int pp = i & 31;
            int k  = i >> 5;
            int gy = py0 + (pp >> 3);
            int gx = px0 + (pp & 7);
            float dy = __ldg(b_off + 2 * k)     + om_s[0][pp][2 * k]     + om_s[1][pp][2 * k];
            float dx = __ldg(b_off + 2 * k + 1) + om_s[0][pp][2 * k + 1] + om_s[1][pp][2 * k + 1];
            float mr = __ldg(b_off + 18 + k)    + om_s[0][pp][18 + k]    + om_s[1][pp][18 + k];
            float mv = 1.f / (1.f + expf(-mr));
            float ysv = (float)gy + (float)(k / 3 - 1) + dy;
            float xsv = (float)gx + (float)(k % 3 - 1) + dx;
            float y0f = floorf(ysv), x0f = floorf(xsv);
            float wy = ysv - y0f, wx = xsv - x0f;
            int y0 = (int)y0f, x0 = (int)x0f;
            int y1 = y0 + 1, x1 = x0 + 1;
            bool vy0 = (y0 >= 0) && (y0 < Hh);
            bool vy1 = (y1 >= 0) && (y1 < Hh);
            bool vx0 = (x0 >= 0) && (x0 < Ww);
            bool vx1 = (x1 >= 0) && (x1 < Ww);
            int y0c = min(max(y0, 0), Hh - 1), y1c = min(max(y1, 0), Hh - 1);
            int x0c = min(max(x0, 0), Ww - 1), x1c = min(max(x1, 0), Ww - 1);
            float4 wv;
            wv.x = (vy0 && vx0) ? mv * (1.f - wy) * (1.f - wx) : 0.f;
            wv.y = (vy0 && vx1) ? mv * (1.f - wy) * wx         : 0.f;
            wv.z = (vy1 && vx0) ? mv * wy * (1.f - wx)         : 0.f;
            wv.w = (vy1 && vx1) ? mv * wy * wx                 : 0.f;
            int4 iv;
            iv.x = y0c * Ww + x0c;
            iv.y = y0c * Ww + x1c;
            iv.z = y1c * Ww + x0c;
            iv.w = y1c * Ww + x1c;
            swgt[i] = wv;
            sidx[i] = iv;
        }
        __syncthreads();
    }

    // ================= Phase 2: sampling + GEMM + epilogue =================
    int to = tid >> 3;   // 0..15 -> o-base = to*16
    int tp = tid & 7;    // 0..7  -> p-base = tp*4

    u64 acc2[8][4];
#pragma unroll
    for (int i = 0; i < 8; i++)
#pragma unroll
        for (int j = 0; j < 4; j++) acc2[i][j] = 0ull;

    const float* xb = x + (size_t)b * Cc * HW;
    u32 wsm_base = smem_u32(smem + WSM_O);

    float pf[5][4];

    // ---- prologue ----
    {
        // cp.async chunk-0 weights -> wsm[0]
        const float4* wp4 = (const float4*)wT;
        u32 wdst = wsm_base + tid * 16;
#pragma unroll
        for (int q = 0; q < 9; q++)
            CP_ASYNC16(wdst + q * 2048, wp4 + tid + NT * q);
        CP_COMMIT();
        // gather chunk-0 samples
#pragma unroll
        for (int q = 0; q < 5; q++) {
            int i = tid + NT * q;
            if (q < 4 || tid < 64) {
                int cc = (i >= NS);
                int r  = i - (cc ? NS : 0);
                int4 iv = sidx[r];
                const float* xp = xb + (size_t)cc * HW;
                pf[q][0] = __ldg(xp + iv.x);
                pf[q][1] = __ldg(xp + iv.y);
                pf[q][2] = __ldg(xp + iv.z);
                pf[q][3] = __ldg(xp + iv.w);
            }
        }
        // commit chunk-0 samples -> ssm[0]
        float* ssm0 = (float*)(smem + SSM_O);
#pragma unroll
        for (int q = 0; q < 5; q++) {
            int i = tid + NT * q;
            if (q < 4 || tid < 64) {
                int cc = (i >= NS);
                int r  = i - (cc ? NS : 0);
                float4 wv = swgt[r];
                ssm0[i] = wv.x * pf[q][0] + wv.y * pf[q][1]
                        + wv.z * pf[q][2] + wv.w * pf[q][3];
            }
        }
        // prefetch chunk-1 samples into pf
        const float* xn = xb + (size_t)2 * HW;
#pragma unroll
        for (int q = 0; q < 5; q++) {
            int i = tid + NT * q;
            if (q < 4 || tid < 64) {
                int cc = (i >= NS);
                int r  = i - (cc ? NS : 0);
                int4 iv = sidx[r];
                const float* xp = xn + (size_t)cc * HW;
                pf[q][0] = __ldg(xp + iv.x);
                pf[q][1] = __ldg(xp + iv.y);
                pf[q][2] = __ldg(xp + iv.z);
                pf[q][3] = __ldg(xp + iv.w);
            }
        }
        CP_WAIT0();
        __syncthreads();
    }

    // ---- main loop: ONE barrier per chunk ----
    for (int j = 0; j < 128; j++) {
        int s = j & 1;

        if (j < 127) {
            // issue next chunk's weights into the idle buffer (completes during GEMM)
            const float4* wp4 = (const float4*)(wT + (size_t)(j + 1) * 2 * 2304);
            u32 wdst = wsm_base + (s ^ 1) * 18432 + tid * 16;
#pragma unroll
            for (int q = 0; q < 9; q++)
                CP_ASYNC16(wdst + q * 2048, wp4 + tid + NT * q);
            CP_COMMIT();
            // commit chunk j+1 samples (pf loaded last chunk) into idle ssm
            float* ssn = (float*)(smem + SSM_O + (s ^ 1) * 2304);
#pragma unroll
            for (int q = 0; q < 5; q++) {
                int i = tid + NT * q;
                if (q < 4 || tid < 64) {
                    int cc = (i >= NS);
                    int r  = i - (cc ? NS : 0);
                    float4 wv = swgt[r];
                    ssn[i] = wv.x * pf[q][0] + wv.y * pf[q][1]
                           + wv.z * pf[q][2] + wv.w * pf[q][3];
                }
            }
            // prefetch chunk j+2 samples into pf (consumed next chunk)
            if (j < 126) {
                const float* xn = xb + (size_t)(j + 2) * 2 * HW;
#pragma unroll
                for (int q = 0; q < 5; q++) {
                    int i = tid + NT * q;
                    if (q < 4 || tid < 64) {
                        int cc = (i >= NS);
                        int r  = i - (cc ? NS : 0);
                        int4 iv = sidx[r];
                        const float* xp = xn + (size_t)cc * HW;
                        pf[q][0] = __ldg(xp + iv.x);
                        pf[q][1] = __ldg(xp + iv.y);
                        pf[q][2] = __ldg(xp + iv.z);
                        pf[q][3] = __ldg(xp + iv.w);
                    }
                }
            }
        }

        // GEMM on current buffers
        const float* wsm = (const float*)(smem + WSM_O + s * 18432);
        const float* ssm = (const float*)(smem + SSM_O + s * 2304);
#pragma unroll
        for (int cc = 0; cc < 2; cc++) {
#pragma unroll
            for (int k = 0; k < 9; k++) {
                const float* wr = wsm + cc * 2304 + k * 256 + (to << 4);
                ulonglong2 w01 = *(const ulonglong2*)(wr);
                ulonglong2 w23 = *(const ulonglong2*)(wr + 4);
                ulonglong2 w45 = *(const ulonglong2*)(wr + 8);
                ulonglong2 w67 = *(const ulonglong2*)(wr + 12);
                float4 sv = *(const float4*)(ssm + cc * NS + k * NPX + (tp << 2));
                u64 sp[4];
                sp[0] = pack2(sv.x, sv.x);
                sp[1] = pack2(sv.y, sv.y);
                sp[2] = pack2(sv.z, sv.z);
                sp[3] = pack2(sv.w, sv.w);
                u64 wp[8] = {w01.x, w01.y, w23.x, w23.y, w45.x, w45.y, w67.x, w67.y};
#pragma unroll
                for (int op = 0; op < 8; op++)
#pragma unroll
                    for (int jj = 0; jj < 4; jj++)
                        FMA2(acc2[op][jj], wp[op], sp[jj]);
            }
        }

        CP_WAIT0();          // next chunk's weights have landed
        __syncthreads();     // single barrier: flips buffers
    }

    // epilogue: bias + ReLU, vectorized stores
    {
        int row = tp >> 1;               // 0..3
        int cb  = (tp & 1) << 2;         // 0 or 4
#pragma unroll
        for (int op = 0; op < 8; op++) {
            int o0 = (to << 4) + (op << 1);
            float bv0 = __ldg(bias + o0);
            float bv1 = __ldg(bias + o0 + 1);
            float2 v0 = unpack2(acc2[op][0]);
            float2 v1 = unpack2(acc2[op][1]);
            float2 v2 = unpack2(acc2[op][2]);
            float2 v3 = unpack2(acc2[op][3]);
            float4 lo, hi;
            lo.x = fmaxf(v0.x + bv0, 0.f); lo.y = fmaxf(v1.x + bv0, 0.f);
            lo.z = fmaxf(v2.x + bv0, 0.f); lo.w = fmaxf(v3.x + bv0, 0.f);
            hi.x = fmaxf(v0.y + bv1, 0.f); hi.y = fmaxf(v1.y + bv1, 0.f);
            hi.z = fmaxf(v2.y + bv1, 0.f); hi.w = fmaxf(v3.y + bv1, 0.f);
            size_t base0 = ((size_t)(b * Onc + o0) * Hh + py0 + row) * Ww + px0 + cb;
            size_t base1 = base0 + (size_t)Hh * Ww;
            *(float4*)(out + base0) = lo;
            *(float4*)(out + base1) = hi;
        }
    }
}

// ---------------------------------------------------------------------------
// Launch
// ---------------------------------------------------------------------------
extern "C" void kernel_launch(void* const* d_in, const int* in_sizes, int n_in,
                              void* d_out, int out_size)
{
    const float* x = (const float*)d_in[0];
    const float* w_off[3] = {(const float*)d_in[1], (const float*)d_in[5], (const float*)d_in[9]};
    const float* b_off[3] = {(const float*)d_in[2], (const float*)d_in[6], (const float*)d_in[10]};
    const float* wq[3]    = {(const float*)d_in[3], (const float*)d_in[7], (const float*)d_in[11]};
    const float* bias[3]  = {(const float*)d_in[4], (const float*)d_in[8], (const float*)d_in[12]};

    float *buf1, *buf2, *wT, *woT;
    cudaGetSymbolAddress((void**)&buf1, g_buf1);
    cudaGetSymbolAddress((void**)&buf2, g_buf2);
    cudaGetSymbolAddress((void**)&wT, g_wT);
    cudaGetSymbolAddress((void**)&woT, g_woT);

    cudaFuncSetAttribute(dcn_fused_kernel, cudaFuncAttributeMaxDynamicSharedMemorySize, SMEMSZ);

    transpose_w_all<<<(3 * Cc * Kk * Onc + 255) / 256, 256>>>(wq[0], wq[1], wq[2], wT);
    transpose_woff_all<<<(3 * Cc * Kk * 28 + 255) / 256, 256>>>(w_off[0], w_off[1], w_off[2], woT);

    const float* src[3] = {x, buf1, buf2};
    float*       dst[3] = {buf1, buf2, (float*)d_out};

    for (int l = 0; l < 3; l++) {
        dcn_fused_kernel<<<dim3(128, Bn), NT, SMEMSZ>>>(src[l],
                                                        woT + (size_t)l * Cc * Kk * 28,
                                                        b_off[l],
                                                        wT + (size_t)l * Cc * Kk * Onc,
                                                        bias[l], dst[l]);
    }
}

// round 15
// speedup vs baseline: 1.2878x; 1.0074x over previous
#include <cuda_runtime.h>
#include <math.h>
#include <cstdint>

#define Bn 4
#define Cc 256
#define Onc 256
#define Hh 64
#define Ww 64
#define Kk 9
#define HW 4096
#define NT 128            // threads per CTA
#define NPX 32            // pixels per tile (4 rows x 8 cols)
#define NS 288            // samples per channel (9 taps x 32 px)

typedef unsigned long long u64;
typedef uint32_t u32;

// Scratch (static device arrays — no allocation)
__device__ float  g_buf1[Bn * Cc * HW];
__device__ float  g_buf2[Bn * Cc * HW];
__device__ float2 g_dup [Bn * Cc * HW];         // pair-duplicated current input (33.5 MB)
__device__ float  g_wT[3 * Cc * Kk * Onc];      // main weights [l][c][k][o]
__device__ float  g_woT[3 * Cc * Kk * 28];      // offset weights [l][c][tap][28]

// ---- packed f32x2 helpers -------------------------------------------------
#define FMA2(d, a, b)  asm("fma.rn.f32x2 %0, %1, %2, %0;" : "+l"(d) : "l"(a), "l"(b))
#define ADDP2(d, a)    asm("add.rn.f32x2 %0, %1, %0;" : "+l"(d) : "l"(a))

__device__ __forceinline__ u64 pack2(float lo, float hi) {
    u64 r; asm("mov.b64 %0, {%1,%2};" : "=l"(r) : "f"(lo), "f"(hi)); return r;
}
__device__ __forceinline__ float2 unpack2(u64 v) {
    float2 f; asm("mov.b64 {%0,%1}, %2;" : "=f"(f.x), "=f"(f.y) : "l"(v)); return f;
}

// ---- cp.async helpers -----------------------------------------------------
__device__ __forceinline__ u32 smem_u32(const void* p) {
    u32 a;
    asm("{ .reg .u64 t; cvta.to.shared.u64 t, %1; cvt.u32.u64 %0, t; }" : "=r"(a) : "l"(p));
    return a;
}
#define CP_ASYNC16(dst, src) \
    asm volatile("cp.async.cg.shared.global [%0], [%1], 16;" :: "r"(dst), "l"(src))
#define CP_COMMIT() asm volatile("cp.async.commit_group;" ::: "memory")
#define CP_WAIT0()  asm volatile("cp.async.wait_group 0;" ::: "memory")

// ---------------------------------------------------------------------------
// Prep kernels
// ---------------------------------------------------------------------------
__global__ void transpose_w_all(const float* __restrict__ w0, const float* __restrict__ w1,
                                const float* __restrict__ w2, float* __restrict__ wT)
{
    int idx = blockIdx.x * blockDim.x + threadIdx.x;
    if (idx >= 3 * Cc * Kk * Onc) return;
    int l   = idx / (Cc * Kk * Onc);
    int rem = idx - l * (Cc * Kk * Onc);
    int o = rem & (Onc - 1);
    int k = (rem >> 8) % Kk;
    int c = rem / (Kk * Onc);
    const float* w = (l == 0) ? w0 : (l == 1) ? w1 : w2;
    wT[idx] = w[((size_t)o * Cc + c) * Kk + k];
}

__global__ void transpose_woff_all(const float* __restrict__ w0, const float* __restrict__ w1,
                                   const float* __restrict__ w2, float* __restrict__ wT)
{
    int idx = blockIdx.x * blockDim.x + threadIdx.x;
    if (idx >= 3 * Cc * Kk * 28) return;
    int l   = idx / (Cc * Kk * 28);
    int rem = idx - l * (Cc * Kk * 28);
    int oc  = rem % 28;
    int tap = (rem / 28) % Kk;
    int c   = rem / (Kk * 28);
    const float* w = (l == 0) ? w0 : (l == 1) ? w1 : w2;
    wT[idx] = (oc < 27) ? w[((size_t)oc * Cc + c) * Kk + tap] : 0.f;
}

// Build pair-duplicated image: dup[i] = (src[i], src[i+1 within row, clamped])
__global__ void dup_kernel(const float* __restrict__ src, float2* __restrict__ dst)
{
    int idx = blockIdx.x * 256 + threadIdx.x;
    if (idx >= Bn * Cc * HW) return;
    int w = idx & (Ww - 1);
    float v0 = src[idx];
    float v1 = (w < Ww - 1) ? src[idx + 1] : v0;
    dst[idx] = make_float2(v0, v1);
}

// ---------------------------------------------------------------------------
// Dynamic smem layout (bytes), total 48384, 4 CTAs/SM:
//   [0,     4608)   swgt float4[288]  (wa0,wb0,wa1,wb1)
//   [4608,  6912)   sidx int2[288]    (row0 index, row1 index into dup plane)
//   [6912,  11520)  ssm[2][576 floats]
//   [11520, 48384)  wsm[2][4608 floats] (cp.async double buffer)
// Phase-1 overlays: xs[16][72] at 0 + wo[16*252] at 4608 (-> 20736);
//                   om[2][32][28] at 20736 (7168).
// ---------------------------------------------------------------------------
#define SWGT_O  0
#define SIDX_O  4608
#define SSM_O   6912
#define WSM_O   11520
#define XS_O    0
#define WO_O    4608
#define OM_O    20736
#define SMEMSZ  48384

__global__ __launch_bounds__(NT, 4) void dcn_fused_kernel(
    const float* __restrict__ x,
    const float2* __restrict__ dup,    // pair-duplicated x
    const float* __restrict__ w_offT,  // [C][9][28]
    const float* __restrict__ b_off,   // [27]
    const float* __restrict__ wT,      // [C][9][O]
    const float* __restrict__ bias,    // [O]
    float* __restrict__ out)
{
    extern __shared__ __align__(16) char smem[];
    float4* swgt  = (float4*)(smem + SWGT_O);
    int2*   sidx2 = (int2*)(smem + SIDX_O);

    int b   = blockIdx.y;
    int t   = blockIdx.x;             // 0..127
    int py0 = (t >> 3) * 4;
    int px0 = (t & 7) * 8;
    int tid = threadIdx.x;

    // ======================== Phase 1: offset conv ========================
    {
        float* xs_s = (float*)(smem + XS_O);           // [16][72] (6x12 halo)
        float* wo_s = (float*)(smem + WO_O);           // [16*252]
        float (*om_s)[NPX][28] = (float (*)[NPX][28])(smem + OM_O);

        int p   = tid & 31;
        int g   = tid >> 5;
        int ppy = p >> 3;
        int ppx = p & 7;

        u64 aoff2[14];
#pragma unroll
        for (int j = 0; j < 14; j++) aoff2[j] = 0ull;

        float  hpf[9];
        float4 wpf[8];

        // prefetch round 0
        {
            const float4* wp4 = (const float4*)w_offT;
#pragma unroll
            for (int i9 = 0; i9 < 9; i9++) {
                int i = tid + NT * i9;
                int ch  = i / 72;
                int rem = i - ch * 72;
                int rr  = rem / 12;
                int cc2 = rem - rr * 12;
                int gy  = py0 - 1 + rr;
                int gx  = px0 - 1 + cc2;
                float v = 0.f;
                if (cc2 < 10 && (unsigned)gy < (unsigned)Hh && (unsigned)gx < (unsigned)Ww)
                    v = __ldg(x + ((size_t)(b * Cc + ch)) * HW + gy * Ww + gx);
                hpf[i9] = v;
            }
#pragma unroll
            for (int i8 = 0; i8 < 8; i8++) {
                int i = tid + NT * i8;
                if (i < 1008) wpf[i8] = __ldg(wp4 + i);
            }
        }

        for (int r = 0; r < 16; r++) {
            __syncthreads();
#pragma unroll
            for (int i9 = 0; i9 < 9; i9++) {
                int i = tid + NT * i9;
                xs_s[i] = hpf[i9];
            }
            {
                float4* wo4 = (float4*)wo_s;
#pragma unroll
                for (int i8 = 0; i8 < 8; i8++) {
                    int i = tid + NT * i8;
                    if (i < 1008) wo4[i] = wpf[i8];
                }
            }
            __syncthreads();

            if (r < 15) {
                int rn = r + 1;
                const float4* wp4 = (const float4*)(w_offT + (size_t)(rn << 4) * 252);
#pragma unroll
                for (int i9 = 0; i9 < 9; i9++) {
                    int i = tid + NT * i9;
                    int ch  = i / 72;
                    int rem = i - ch * 72;
                    int rr  = rem / 12;
                    int cc2 = rem - rr * 12;
                    int c   = (rn << 4) + ch;
                    int gy  = py0 - 1 + rr;
                    int gx  = px0 - 1 + cc2;
                    float v = 0.f;
                    if (cc2 < 10 && (unsigned)gy < (unsigned)Hh && (unsigned)gx < (unsigned)Ww)
                        v = __ldg(x + ((size_t)(b * Cc + c)) * HW + gy * Ww + gx);
                    hpf[i9] = v;
                }
#pragma unroll
                for (int i8 = 0; i8 < 8; i8++) {
                    int i = tid + NT * i8;
                    if (i < 1008) wpf[i8] = __ldg(wp4 + i);
                }
            }

#pragma unroll
            for (int ci = 0; ci < 4; ci++) {
                int ch = (g << 2) + ci;
                const float* xrow = xs_s + ch * 72;
                float xv[9];
#pragma unroll
                for (int rr = 0; rr < 3; rr++)
#pragma unroll
                    for (int cc = 0; cc < 3; cc++)
                        xv[rr * 3 + cc] = xrow[(ppy + rr) * 12 + ppx + cc];

#pragma unroll
                for (int tap = 0; tap < 9; tap++) {
                    u64 xt2 = pack2(xv[tap], xv[tap]);
                    const ulonglong2* wr = (const ulonglong2*)(wo_s + ch * 252 + tap * 28);
#pragma unroll
                    for (int j = 0; j < 7; j++) {
                        ulonglong2 wv2 = wr[j];
                        FMA2(aoff2[2 * j],     xt2, wv2.x);
                        FMA2(aoff2[2 * j + 1], xt2, wv2.y);
                    }
                }
            }
        }
        __syncthreads();
        if (g >= 2) {
#pragma unroll
            for (int j = 0; j < 14; j++)
                *(u64*)&om_s[g - 2][p][2 * j] = aoff2[j];
        }
        __syncthreads();
        if (g < 2) {
#pragma unroll
            for (int j = 0; j < 14; j++) {
                u64 tacc = *(u64*)&om_s[g][p][2 * j];
                ADDP2(tacc, aoff2[j]);
                *(u64*)&om_s[g][p][2 * j] = tacc;
            }
        }
        __syncthreads();

        // ---- Coordinate / pair-gather weight precompute ----
        for (int i = tid; i < NS; i += NT) {
            int pp = i & 31;
            int k  = i >> 5;
            int gy = py0 + (pp >> 3);
            int gx = px0 + (pp & 7);
            float dy = __ldg(b_off + 2 * k)     + om_s[0][pp][2 * k]     + om_s[1][pp][2 * k];
            float dx = __ldg(b_off + 2 * k + 1) + om_s[0][pp][2 * k + 1] + om_s[1][pp][2 * k + 1];
            float mr = __ldg(b_off + 18 + k)    + om_s[0][pp][18 + k]    + om_s[1][pp][18 + k];
            float mv = 1.f / (1.f + expf(-mr));
            float ysv = (float)gy + (float)(k / 3 - 1) + dy;
            float xsv = (float)gx + (float)(k % 3 - 1) + dx;
            float y0f = floorf(ysv), x0f = floorf(xsv);
            float wy = ysv - y0f, wx = xsv - x0f;
            int y0 = (int)y0f, x0 = (int)x0f;
            int y1 = y0 + 1, x1 = x0 + 1;
            float r0 = ((y0 >= 0) && (y0 < Hh)) ? mv * (1.f - wy) : 0.f;
            float r1 = ((y1 >= 0) && (y1 < Hh)) ? mv * wy         : 0.f;
            int y0c = min(max(y0, 0), Hh - 1), y1c = min(max(y1, 0), Hh - 1);
            int xd; float ca, cb;
            if (x0 < 0)            { xd = 0;  ca = (x1 == 0) ? wx : 0.f; cb = 0.f; }
            else if (x0 >= Ww)     { xd = 0;  ca = 0.f;                  cb = 0.f; }
            else                   { xd = x0; ca = 1.f - wx;  cb = (x1 < Ww) ? wx : 0.f; }
            float4 wv;
            wv.x = r0 * ca;   // row0 pair.x
            wv.y = r0 * cb;   // row0 pair.y
            wv.z = r1 * ca;   // row1 pair.x
            wv.w = r1 * cb;   // row1 pair.y
            int2 iv;
            iv.x = y0c * Ww + xd;
            iv.y = y1c * Ww + xd;
            swgt[i]  = wv;
            sidx2[i] = iv;
        }
        __syncthreads();
    }

    // ================= Phase 2: sampling + GEMM + epilogue =================
    int to = tid >> 3;   // 0..15 -> o-base = to*16
    int tp = tid & 7;    // 0..7  -> p-base = tp*4

    u64 acc2[8][4];
#pragma unroll
    for (int i = 0; i < 8; i++)
#pragma unroll
        for (int j = 0; j < 4; j++) acc2[i][j] = 0ull;

    const float2* db = dup + (size_t)b * Cc * HW;
    u32 wsm_base = smem_u32(smem + WSM_O);

    float2 pfA[5], pfB[5];

    // ---- prologue ----
    {
        const float4* wp4 = (const float4*)wT;
        u32 wdst = wsm_base + tid * 16;
#pragma unroll
        for (int q = 0; q < 9; q++)
            CP_ASYNC16(wdst + q * 2048, wp4 + tid + NT * q);
        CP_COMMIT();
        // gather chunk-0 samples (2 x LDG.64 each)
#pragma unroll
        for (int q = 0; q < 5; q++) {
            int i = tid + NT * q;
            if (q < 4 || tid < 64) {
                int cc = (i >= NS);
                int r  = i - (cc ? NS : 0);
                int2 iv = sidx2[r];
                const float2* dp = db + (size_t)cc * HW;
                pfA[q] = __ldg(dp + iv.x);
                pfB[q] = __ldg(dp + iv.y);
            }
        }
        // commit chunk-0 samples -> ssm[0]
        float* ssm0 = (float*)(smem + SSM_O);
#pragma unroll
        for (int q = 0; q < 5; q++) {
            int i = tid + NT * q;
            if (q < 4 || tid < 64) {
                int cc = (i >= NS);
                int r  = i - (cc ? NS : 0);
                float4 wv = swgt[r];
                ssm0[i] = wv.x * pfA[q].x + wv.y * pfA[q].y
                        + wv.z * pfB[q].x + wv.w * pfB[q].y;
            }
        }
        // prefetch chunk-1 samples
        const float2* dn = db + (size_t)2 * HW;
#pragma unroll
        for (int q = 0; q < 5; q++) {
            int i = tid + NT * q;
            if (q < 4 || tid < 64) {
                int cc = (i >= NS);
                int r  = i - (cc ? NS : 0);
                int2 iv = sidx2[r];
                const float2* dp = dn + (size_t)cc * HW;
                pfA[q] = __ldg(dp + iv.x);
                pfB[q] = __ldg(dp + iv.y);
            }
        }
        CP_WAIT0();
        __syncthreads();
    }

    // ---- main loop: ONE barrier per chunk ----
    for (int j = 0; j < 128; j++) {
        int s = j & 1;

        if (j < 127) {
            const float4* wp4 = (const float4*)(wT + (size_t)(j + 1) * 2 * 2304);
            u32 wdst = wsm_base + (s ^ 1) * 18432 + tid * 16;
#pragma unroll
            for (int q = 0; q < 9; q++)
                CP_ASYNC16(wdst + q * 2048, wp4 + tid + NT * q);
            CP_COMMIT();
            float* ssn = (float*)(smem + SSM_O + (s ^ 1) * 2304);
#pragma unroll
            for (int q = 0; q < 5; q++) {
                int i = tid + NT * q;
                if (q < 4 || tid < 64) {
                    int cc = (i >= NS);
                    int r  = i - (cc ? NS : 0);
                    float4 wv = swgt[r];
                    ssn[i] = wv.x * pfA[q].x + wv.y * pfA[q].y
                           + wv.z * pfB[q].x + wv.w * pfB[q].y;
                }
            }
            if (j < 126) {
                const float2* dn = db + (size_t)(j + 2) * 2 * HW;
#pragma unroll
                for (int q = 0; q < 5; q++) {
                    int i = tid + NT * q;
                    if (q < 4 || tid < 64) {
                        int cc = (i >= NS);
                        int r  = i - (cc ? NS : 0);
                        int2 iv = sidx2[r];
                        const float2* dp = dn + (size_t)cc * HW;
                        pfA[q] = __ldg(dp + iv.x);
                        pfB[q] = __ldg(dp + iv.y);
                    }
                }
            }
        }

        // GEMM on current buffers
        const float* wsm = (const float*)(smem + WSM_O + s * 18432);
        const float* ssm = (const float*)(smem + SSM_O + s * 2304);
#pragma unroll
        for (int cc = 0; cc < 2; cc++) {
#pragma unroll
            for (int k = 0; k < 9; k++) {
                const float* wr = wsm + cc * 2304 + k * 256 + (to << 4);
                ulonglong2 w01 = *(const ulonglong2*)(wr);
                ulonglong2 w23 = *(const ulonglong2*)(wr + 4);
                ulonglong2 w45 = *(const ulonglong2*)(wr + 8);
                ulonglong2 w67 = *(const ulonglong2*)(wr + 12);
                float4 sv = *(const float4*)(ssm + cc * NS + k * NPX + (tp << 2));
                u64 sp[4];
                sp[0] = pack2(sv.x, sv.x);
                sp[1] = pack2(sv.y, sv.y);
                sp[2] = pack2(sv.z, sv.z);
                sp[3] = pack2(sv.w, sv.w);
                u64 wp[8] = {w01.x, w01.y, w23.x, w23.y, w45.x, w45.y, w67.x, w67.y};
#pragma unroll
                for (int op = 0; op < 8; op++)
#pragma unroll
                    for (int jj = 0; jj < 4; jj++)
                        FMA2(acc2[op][jj], wp[op], sp[jj]);
            }
        }

        CP_WAIT0();
        __syncthreads();
    }

    // epilogue: bias + ReLU, vectorized stores
    {
        int row = tp >> 1;
        int cb  = (tp & 1) << 2;
#pragma unroll
        for (int op = 0; op < 8; op++) {
            int o0 = (to << 4) + (op << 1);
            float bv0 = __ldg(bias + o0);
            float bv1 = __ldg(bias + o0 + 1);
            float2 v0 = unpack2(acc2[op][0]);
            float2 v1 = unpack2(acc2[op][1]);
            float2 v2 = unpack2(acc2[op][2]);
            float2 v3 = unpack2(acc2[op][3]);
            float4 lo, hi;
            lo.x = fmaxf(v0.x + bv0, 0.f); lo.y = fmaxf(v1.x + bv0, 0.f);
            lo.z = fmaxf(v2.x + bv0, 0.f); lo.w = fmaxf(v3.x + bv0, 0.f);
            hi.x = fmaxf(v0.y + bv1, 0.f); hi.y = fmaxf(v1.y + bv1, 0.f);
            hi.z = fmaxf(v2.y + bv1, 0.f); hi.w = fmaxf(v3.y + bv1, 0.f);
            size_t base0 = ((size_t)(b * Onc + o0) * Hh + py0 + row) * Ww + px0 + cb;
            size_t base1 = base0 + (size_t)Hh * Ww;
            *(float4*)(out + base0) = lo;
            *(float4*)(out + base1) = hi;
        }
    }
}

// ---------------------------------------------------------------------------
// Launch
// ---------------------------------------------------------------------------
extern "C" void kernel_launch(void* const* d_in, const int* in_sizes, int n_in,
                              void* d_out, int out_size)
{
    const float* x = (const float*)d_in[0];
    const float* w_off[3] = {(const float*)d_in[1], (const float*)d_in[5], (const float*)d_in[9]};
    const float* b_off[3] = {(const float*)d_in[2], (const float*)d_in[6], (const float*)d_in[10]};
    const float* wq[3]    = {(const float*)d_in[3], (const float*)d_in[7], (const float*)d_in[11]};
    const float* bias[3]  = {(const float*)d_in[4], (const float*)d_in[8], (const float*)d_in[12]};

    float *buf1, *buf2, *wT, *woT;
    float2* dupb;
    cudaGetSymbolAddress((void**)&buf1, g_buf1);
    cudaGetSymbolAddress((void**)&buf2, g_buf2);
    cudaGetSymbolAddress((void**)&dupb, g_dup);
    cudaGetSymbolAddress((void**)&wT, g_wT);
    cudaGetSymbolAddress((void**)&woT, g_woT);

    cudaFuncSetAttribute(dcn_fused_kernel, cudaFuncAttributeMaxDynamicSharedMemorySize, SMEMSZ);

    transpose_w_all<<<(3 * Cc * Kk * Onc + 255) / 256, 256>>>(wq[0], wq[1], wq[2], wT);
    transpose_woff_all<<<(3 * Cc * Kk * 28 + 255) / 256, 256>>>(w_off[0], w_off[1], w_off[2], woT);

    const float* src[3] = {x, buf1, buf2};
    float*       dst[3] = {buf1, buf2, (float*)d_out};

    for (int l = 0; l < 3; l++) {
        dup_kernel<<<(Bn * Cc * HW + 255) / 256, 256>>>(src[l], dupb);
        dcn_fused_kernel<<<dim3(128, Bn), NT, SMEMSZ>>>(src[l], dupb,
                                                        woT + (size_t)l * Cc * Kk * 28,
                                                        b_off[l],
                                                        wT + (size_t)l * Cc * Kk * Onc,
                                                        bias[l], dst[l]);
    }
}